// round 3
// baseline (speedup 1.0000x reference)
#include <cuda_runtime.h>
#include <cuda_bf16.h>
#include <cstdint>

// VQ forward via mma.sync (HMMA) bf16-split GEMM + exact fp32 rescoring.
//   inputs [64,1024,64] f32, embedding [512,64] f32
//   out = [loss(1) | quantized_st(65536*64) | perplexity(1) | indices(65536)] f32

#define KN 512
#define DN 64
#define TM 128          // tokens per CTA
#define NTHREADS 256

// ---- smem layout (bytes), all SW128-swizzled bf16 tiles are 128B/row ----
#define AHI_OFF   0            // [128 x 128B] X hi
#define ALO_OFF   16384        // [128 x 128B] X lo
#define BHI_OFF   32768        // [512 x 128B] E hi
#define BLO_OFF   98304        // [512 x 128B] E lo
#define XS_OFF    163840       // [128 x 64] f32 staged X
#define BN_OFF    196608       // [512] f32 ||e||^2
#define AN_OFF    198656       // [128] f32 ||x||^2
#define KA_OFF    199168       // [128] int chosen code
#define HIST_OFF  199680       // [512] u32
#define CAND_OFF  201728       // [128][8] uint4 (s0,k0,s1,k1)
#define SMEM_TOTAL 218112

__device__ double       g_err_sum;
__device__ unsigned int g_counts[KN];

__global__ void vq_zero() {
    int t = threadIdx.x;
    if (t == 0) g_err_sum = 0.0;
    if (t < KN) g_counts[t] = 0u;
}

__device__ __forceinline__ uint32_t smem_u32(const void* p) {
    uint32_t a;
    asm("{ .reg .u64 t; cvta.to.shared.u64 t, %1; cvt.u32.u64 %0, t; }" : "=r"(a) : "l"(p));
    return a;
}
__device__ __forceinline__ void ldsm4(uint32_t addr, uint32_t* r) {
    asm volatile("ldmatrix.sync.aligned.m8n8.x4.shared.b16 {%0,%1,%2,%3}, [%4];"
                 : "=r"(r[0]), "=r"(r[1]), "=r"(r[2]), "=r"(r[3]) : "r"(addr));
}
__device__ __forceinline__ void mma16816(float* d, const uint32_t* a, const uint32_t* b) {
    asm volatile("mma.sync.aligned.m16n8k16.row.col.f32.bf16.bf16.f32 "
                 "{%0,%1,%2,%3}, {%4,%5,%6,%7}, {%8,%9}, {%0,%1,%2,%3};"
                 : "+f"(d[0]), "+f"(d[1]), "+f"(d[2]), "+f"(d[3])
                 : "r"(a[0]), "r"(a[1]), "r"(a[2]), "r"(a[3]), "r"(b[0]), "r"(b[1]));
}
__device__ __forceinline__ uint32_t swaddr(uint32_t base, int row, int bc) {
    return base + row * 128 + (bc ^ ((row & 7) << 4));
}

// pack 8 consecutive floats -> 8 bf16 hi + 8 bf16 lo (residual)
__device__ __forceinline__ void pack8(const float4 a, const float4 b, uint4& hi, uint4& lo) {
    float f[8] = {a.x, a.y, a.z, a.w, b.x, b.y, b.z, b.w};
    unsigned short h[8], l[8];
    #pragma unroll
    for (int i = 0; i < 8; i++) {
        __nv_bfloat16 hb = __float2bfloat16_rn(f[i]);
        float r = __fsub_rn(f[i], __bfloat162float(hb));
        h[i] = __bfloat16_as_ushort(hb);
        l[i] = __bfloat16_as_ushort(__float2bfloat16_rn(r));
    }
    hi = make_uint4((uint32_t)h[0] | ((uint32_t)h[1] << 16), (uint32_t)h[2] | ((uint32_t)h[3] << 16),
                    (uint32_t)h[4] | ((uint32_t)h[5] << 16), (uint32_t)h[6] | ((uint32_t)h[7] << 16));
    lo = make_uint4((uint32_t)l[0] | ((uint32_t)l[1] << 16), (uint32_t)l[2] | ((uint32_t)l[3] << 16),
                    (uint32_t)l[4] | ((uint32_t)l[5] << 16), (uint32_t)l[6] | ((uint32_t)l[7] << 16));
}

// exact reference-order distance (validated bit-exact in round 1)
__device__ __forceinline__ float exact_d(const float* __restrict__ xp,
                                         const float* __restrict__ emb,
                                         float A, float bnk, int k) {
    const float4* ep = (const float4*)(emb + (size_t)k * DN);
    float dot = 0.f;
    #pragma unroll
    for (int i = 0; i < 16; i++) {
        float4 e4 = __ldg(ep + i);
        const float4 x4 = *(const float4*)(xp + 4 * i);
        dot = __fmaf_rn(x4.x, e4.x, dot);
        dot = __fmaf_rn(x4.y, e4.y, dot);
        dot = __fmaf_rn(x4.z, e4.z, dot);
        dot = __fmaf_rn(x4.w, e4.w, dot);
    }
    return __fsub_rn(__fadd_rn(A, bnk), __fmul_rn(2.0f, dot));
}

__device__ __forceinline__ void merge2(float& s0, int& k0, float& s1, int& k1, float s, int k) {
    if (s < s0 || (s == s0 && k < k0)) { s1 = s0; k1 = k0; s0 = s; k0 = k; }
    else if (s < s1 || (s == s1 && k < k1)) { s1 = s; k1 = k; }
}
__device__ __forceinline__ void ins4(float* s, int* k, float sv, int kv) {
    if (sv < s[3] || (sv == s[3] && kv < k[3])) {
        s[3] = sv; k[3] = kv;
        #pragma unroll
        for (int i = 3; i > 0; i--) {
            if (s[i] < s[i-1] || (s[i] == s[i-1] && k[i] < k[i-1])) {
                float ts = s[i]; s[i] = s[i-1]; s[i-1] = ts;
                int   tk = k[i]; k[i] = k[i-1]; k[i-1] = tk;
            }
        }
    }
}

__global__ void __launch_bounds__(NTHREADS, 1)
vq_main(const float* __restrict__ x, const float* __restrict__ emb,
        float* __restrict__ out_q, float* __restrict__ out_idx, int ntok)
{
    extern __shared__ __align__(1024) char smem[];
    const uint32_t sbase = smem_u32(smem);
    const int tid  = threadIdx.x;
    const int lane = tid & 31;
    const int wid  = tid >> 5;
    const int tok0 = blockIdx.x * TM;

    float* xs = (float*)(smem + XS_OFF);
    float* bn = (float*)(smem + BN_OFF);
    float* an = (float*)(smem + AN_OFF);
    int*   ka = (int*)(smem + KA_OFF);
    unsigned int* hist = (unsigned int*)(smem + HIST_OFF);
    uint4* cand = (uint4*)(smem + CAND_OFF);

    // ---- prologue: convert X and E to (hi, lo) bf16 SW128 tiles; stage X f32 ----
    for (int idx = tid; idx < TM * DN / 8; idx += NTHREADS) {
        int row = idx >> 3;
        int c8  = (idx & 7) * 8;
        const float* gp = x + (size_t)(tok0 + row) * DN + c8;
        float4 f0 = __ldg((const float4*)gp);
        float4 f1 = __ldg((const float4*)gp + 1);
        float* xr = xs + row * DN + c8;
        *(float4*)xr = f0; *(float4*)(xr + 4) = f1;
        uint4 hi, lo; pack8(f0, f1, hi, lo);
        uint32_t off = (uint32_t)row * 128u + (uint32_t)c8 * 2u;
        uint32_t sw  = off ^ ((off >> 3) & 0x70);
        *(uint4*)(smem + AHI_OFF + sw) = hi;
        *(uint4*)(smem + ALO_OFF + sw) = lo;
    }
    for (int idx = tid; idx < KN * DN / 8; idx += NTHREADS) {
        int row = idx >> 3;
        int c8  = (idx & 7) * 8;
        const float* gp = emb + (size_t)row * DN + c8;
        float4 f0 = __ldg((const float4*)gp);
        float4 f1 = __ldg((const float4*)gp + 1);
        uint4 hi, lo; pack8(f0, f1, hi, lo);
        uint32_t off = (uint32_t)row * 128u + (uint32_t)c8 * 2u;
        uint32_t sw  = off ^ ((off >> 3) & 0x70);
        *(uint4*)(smem + BHI_OFF + sw) = hi;
        *(uint4*)(smem + BLO_OFF + sw) = lo;
    }
    for (int t = tid; t < KN; t += NTHREADS) hist[t] = 0u;
    __syncthreads();

    // ---- norms (exact reference rounding order) ----
    for (int k = tid; k < KN; k += NTHREADS) {
        const float* ep = emb + (size_t)k * DN;
        float s = 0.f;
        #pragma unroll
        for (int i = 0; i < DN; i++) s = __fadd_rn(s, __fmul_rn(ep[i], ep[i]));
        bn[k] = s;
    }
    for (int t = tid; t < TM; t += NTHREADS) {
        const float* xp = xs + t * DN;
        float s = 0.f;
        #pragma unroll
        for (int i = 0; i < DN; i++) s = __fadd_rn(s, __fmul_rn(xp[i], xp[i]));
        an[t] = s;
    }
    __syncthreads();

    // ---- MMA: warp wid owns codes [wid*64, wid*64+64), loops 4 M-chunks of 32 tokens ----
    const int wbase = wid * 64;
    const int mat = lane >> 3;
    const int r8  = lane & 7;
    const int c2  = (lane & 3) * 2;

    // preload this thread's 16 bn values (codes wbase + ni*8 + c2 + {0,1})
    float bnr[16];
    #pragma unroll
    for (int ni = 0; ni < 8; ni++) {
        bnr[ni * 2]     = bn[wbase + ni * 8 + c2];
        bnr[ni * 2 + 1] = bn[wbase + ni * 8 + c2 + 1];
    }

    #pragma unroll 1
    for (int m = 0; m < 4; m++) {
        float acc[64];
        #pragma unroll
        for (int i = 0; i < 64; i++) acc[i] = 0.f;

        #pragma unroll
        for (int prod = 0; prod < 3; prod++) {
            uint32_t Ab = sbase + (prod == 2 ? ALO_OFF : AHI_OFF);
            uint32_t Bb = sbase + (prod == 1 ? BLO_OFF : BHI_OFF);
            #pragma unroll
            for (int ks = 0; ks < 4; ks++) {
                uint32_t a[2][4], b[8][2];
                #pragma unroll
                for (int mi = 0; mi < 2; mi++) {
                    int row = m * 32 + mi * 16 + (mat & 1) * 8 + r8;
                    int bc  = ks * 32 + (mat >> 1) * 16;
                    ldsm4(swaddr(Ab, row, bc), a[mi]);
                }
                #pragma unroll
                for (int q = 0; q < 4; q++) {
                    uint32_t t4[4];
                    int row = wbase + q * 16 + (mat >> 1) * 8 + r8;
                    int bc  = ks * 32 + (mat & 1) * 16;
                    ldsm4(swaddr(Bb, row, bc), t4);
                    b[2*q][0] = t4[0]; b[2*q][1] = t4[1];
                    b[2*q+1][0] = t4[2]; b[2*q+1][1] = t4[3];
                }
                #pragma unroll
                for (int mi = 0; mi < 2; mi++)
                    #pragma unroll
                    for (int ni = 0; ni < 8; ni++)
                        mma16816(&acc[(mi * 8 + ni) * 4], a[mi], b[ni]);
            }
        }

        // per-token-row top-2 within this warp's 64 codes
        #pragma unroll
        for (int mi = 0; mi < 2; mi++) {
            #pragma unroll
            for (int half = 0; half < 2; half++) {
                float s0 = 3e38f, s1 = 3e38f;
                int   k0 = 0x7fffffff, k1 = 0x7fffffff;
                #pragma unroll
                for (int ni = 0; ni < 8; ni++) {
                    float d0 = acc[(mi * 8 + ni) * 4 + half * 2 + 0];
                    float d1 = acc[(mi * 8 + ni) * 4 + half * 2 + 1];
                    int kk = wbase + ni * 8 + c2;
                    merge2(s0, k0, s1, k1, __fmaf_rn(-2.f, d0, bnr[ni*2]),   kk);
                    merge2(s0, k0, s1, k1, __fmaf_rn(-2.f, d1, bnr[ni*2+1]), kk + 1);
                }
                #pragma unroll
                for (int off = 1; off <= 2; off <<= 1) {
                    float os0 = __shfl_xor_sync(0xffffffffu, s0, off);
                    int   ok0 = __shfl_xor_sync(0xffffffffu, k0, off);
                    float os1 = __shfl_xor_sync(0xffffffffu, s1, off);
                    int   ok1 = __shfl_xor_sync(0xffffffffu, k1, off);
                    merge2(s0, k0, s1, k1, os0, ok0);
                    merge2(s0, k0, s1, k1, os1, ok1);
                }
                if ((lane & 3) == 0) {
                    int tok = m * 32 + mi * 16 + half * 8 + (lane >> 2);
                    cand[tok * 8 + wid] = make_uint4(__float_as_uint(s0), (uint32_t)k0,
                                                     __float_as_uint(s1), (uint32_t)k1);
                }
            }
        }
    }
    __syncthreads();

    // ---- global merge (top-4 of 16) + exact rescoring; token t = tid < 128 ----
    if (tid < TM) {
        float s[4] = {3e38f, 3e38f, 3e38f, 3e38f};
        int   k[4] = {0x7fffffff, 0x7fffffff, 0x7fffffff, 0x7fffffff};
        #pragma unroll
        for (int w = 0; w < 8; w++) {
            uint4 c = cand[tid * 8 + w];
            ins4(s, k, __uint_as_float(c.x), (int)c.y);
            ins4(s, k, __uint_as_float(c.z), (int)c.w);
        }
        const float A = an[tid];
        const float* xp = xs + tid * DN;
        float bd = 3e38f;
        int   bk = 0x7fffffff;
        #pragma unroll
        for (int i = 0; i < 4; i++) {
            float d = exact_d(xp, emb, A, bn[k[i]], k[i]);
            if (d < bd || (d == bd && k[i] < bk)) { bd = d; bk = k[i]; }
        }
        ka[tid] = bk;
        out_idx[tok0 + tid] = (float)bk;
        atomicAdd(&hist[bk], 1u);
    }
    __syncthreads();

    // ---- gather + straight-through write + err sum (8 warps × 16 tokens) ----
    float err = 0.f;
    #pragma unroll 1
    for (int t = wid * 16; t < wid * 16 + 16; t++) {
        int k = ka[t];
        const float* er = emb + (size_t)k * DN;
        const float* xr = xs + t * DN;
        float x0 = xr[lane], x1 = xr[32 + lane];
        float q0 = __ldg(er + lane), q1 = __ldg(er + 32 + lane);
        float d0 = __fsub_rn(q0, x0);
        float d1 = __fsub_rn(q1, x1);
        out_q[(size_t)(tok0 + t) * DN + lane]      = __fadd_rn(x0, d0);
        out_q[(size_t)(tok0 + t) * DN + 32 + lane] = __fadd_rn(x1, d1);
        err = __fmaf_rn(d0, d0, __fmaf_rn(d1, d1, err));
    }
    #pragma unroll
    for (int off = 16; off > 0; off >>= 1)
        err += __shfl_xor_sync(0xffffffffu, err, off);
    if (lane == 0) atomicAdd(&g_err_sum, (double)err);

    for (int t = tid; t < KN; t += NTHREADS) {
        unsigned int c = hist[t];
        if (c) atomicAdd(&g_counts[t], c);
    }
}

__global__ void vq_fin(float* __restrict__ out_loss, float* __restrict__ out_perp, int ntok)
{
    if (threadIdx.x == 0) {
        double total = (double)ntok * (double)DN;
        float m = (float)(g_err_sum / total);
        out_loss[0] = __fadd_rn(m, __fmul_rn(0.25f, m));
        float s = 0.f;
        float invN = 1.0f / (float)ntok;
        for (int k = 0; k < KN; k++) {
            float p = (float)g_counts[k] * invN;
            s = __fmaf_rn(p, logf(__fadd_rn(p, 1e-10f)), s);
        }
        out_perp[0] = expf(-s);
    }
}

extern "C" void kernel_launch(void* const* d_in, const int* in_sizes, int n_in,
                              void* d_out, int out_size)
{
    const float* x   = (const float*)d_in[0];
    const float* emb = (const float*)d_in[1];
    const int ntok = in_sizes[0] / DN;   // 65536

    float* out      = (float*)d_out;
    float* out_q    = out + 1;
    float* out_perp = out + 1 + (size_t)ntok * DN;
    float* out_idx  = out + 2 + (size_t)ntok * DN;

    cudaFuncSetAttribute(vq_main, cudaFuncAttributeMaxDynamicSharedMemorySize, SMEM_TOTAL);

    vq_zero<<<1, 512>>>();
    vq_main<<<ntok / TM, NTHREADS, SMEM_TOTAL>>>(x, emb, out_q, out_idx, ntok);
    vq_fin<<<1, 32>>>(out, out_perp, ntok);
}

// round 4
// speedup vs baseline: 1.4971x; 1.4971x over previous
#include <cuda_runtime.h>
#include <cuda_bf16.h>
#include <cstdint>

// Fused VQ forward: HMMA bf16-split GEMM + exact fp32 rescoring, persistent grid.
//   inputs [64,1024,64] f32, embedding [512,64] f32
//   out = [loss(1) | quantized_st(65536*64) | perplexity(1) | indices(65536)] f32

#define KN 512
#define DN 64
#define TM 128          // tokens per tile
#define NTHREADS 256
#define NBLK 148

// ---- smem layout (bytes) ----
#define AHI_OFF   0            // [128 x 128B] X hi (SW128)
#define ALO_OFF   16384        // [128 x 128B] X lo
#define BHI_OFF   32768        // [512 x 128B] E hi
#define BLO_OFF   98304        // [512 x 128B] E lo
#define XS_OFF    163840       // [128 x 64] f32 staged X
#define BN_OFF    196608       // [512] f32 ||e||^2
#define KA_OFF    198656       // [128] int chosen code
#define HIST_OFF  199168       // [512] u32 local histogram
#define CAND_OFF  201216       // [128][8] uint4 (s0,k0,s1,k1)
#define SMEM_TOTAL 217600

__device__ double       g_err_sum;
__device__ unsigned int g_counts[KN];
__device__ unsigned int g_done;

__device__ __forceinline__ uint32_t smem_u32(const void* p) {
    uint32_t a;
    asm("{ .reg .u64 t; cvta.to.shared.u64 t, %1; cvt.u32.u64 %0, t; }" : "=r"(a) : "l"(p));
    return a;
}
__device__ __forceinline__ void ldsm4(uint32_t addr, uint32_t* r) {
    asm volatile("ldmatrix.sync.aligned.m8n8.x4.shared.b16 {%0,%1,%2,%3}, [%4];"
                 : "=r"(r[0]), "=r"(r[1]), "=r"(r[2]), "=r"(r[3]) : "r"(addr));
}
__device__ __forceinline__ void mma16816(float* d, const uint32_t* a, const uint32_t* b) {
    asm volatile("mma.sync.aligned.m16n8k16.row.col.f32.bf16.bf16.f32 "
                 "{%0,%1,%2,%3}, {%4,%5,%6,%7}, {%8,%9}, {%0,%1,%2,%3};"
                 : "+f"(d[0]), "+f"(d[1]), "+f"(d[2]), "+f"(d[3])
                 : "r"(a[0]), "r"(a[1]), "r"(a[2]), "r"(a[3]), "r"(b[0]), "r"(b[1]));
}
__device__ __forceinline__ uint32_t swaddr(uint32_t base, int row, int bc) {
    return base + row * 128 + (bc ^ ((row & 7) << 4));
}

__device__ __forceinline__ void pack8(const float4 a, const float4 b, uint4& hi, uint4& lo) {
    float f[8] = {a.x, a.y, a.z, a.w, b.x, b.y, b.z, b.w};
    unsigned short h[8], l[8];
    #pragma unroll
    for (int i = 0; i < 8; i++) {
        __nv_bfloat16 hb = __float2bfloat16_rn(f[i]);
        float r = __fsub_rn(f[i], __bfloat162float(hb));
        h[i] = __bfloat16_as_ushort(hb);
        l[i] = __bfloat16_as_ushort(__float2bfloat16_rn(r));
    }
    hi = make_uint4((uint32_t)h[0] | ((uint32_t)h[1] << 16), (uint32_t)h[2] | ((uint32_t)h[3] << 16),
                    (uint32_t)h[4] | ((uint32_t)h[5] << 16), (uint32_t)h[6] | ((uint32_t)h[7] << 16));
    lo = make_uint4((uint32_t)l[0] | ((uint32_t)l[1] << 16), (uint32_t)l[2] | ((uint32_t)l[3] << 16),
                    (uint32_t)l[4] | ((uint32_t)l[5] << 16), (uint32_t)l[6] | ((uint32_t)l[7] << 16));
}

// exact reference-order distance (validated bit-exact vs reference in round 1)
__device__ __forceinline__ float exact_d(const float* __restrict__ xp,
                                         const float* __restrict__ emb,
                                         float A, float bnk, int k) {
    const float4* ep = (const float4*)(emb + (size_t)k * DN);
    float dot = 0.f;
    #pragma unroll
    for (int i = 0; i < 16; i++) {
        float4 e4 = __ldg(ep + i);
        const float4 x4 = *(const float4*)(xp + 4 * i);
        dot = __fmaf_rn(x4.x, e4.x, dot);
        dot = __fmaf_rn(x4.y, e4.y, dot);
        dot = __fmaf_rn(x4.z, e4.z, dot);
        dot = __fmaf_rn(x4.w, e4.w, dot);
    }
    return __fsub_rn(__fadd_rn(A, bnk), __fmul_rn(2.0f, dot));
}

__device__ __forceinline__ void merge2(float& s0, int& k0, float& s1, int& k1, float s, int k) {
    if (s < s0 || (s == s0 && k < k0)) { s1 = s0; k1 = k0; s0 = s; k0 = k; }
    else if (s < s1 || (s == s1 && k < k1)) { s1 = s; k1 = k; }
}
__device__ __forceinline__ void ins4(float* s, int* k, float sv, int kv) {
    if (sv < s[3] || (sv == s[3] && kv < k[3])) {
        s[3] = sv; k[3] = kv;
        #pragma unroll
        for (int i = 3; i > 0; i--) {
            if (s[i] < s[i-1] || (s[i] == s[i-1] && k[i] < k[i-1])) {
                float ts = s[i]; s[i] = s[i-1]; s[i-1] = ts;
                int   tk = k[i]; k[i] = k[i-1]; k[i-1] = tk;
            }
        }
    }
}

__global__ void __launch_bounds__(NTHREADS, 1)
vq_all(const float* __restrict__ x, const float* __restrict__ emb,
       float* __restrict__ out, int ntok)
{
    extern __shared__ __align__(1024) char smem[];
    const uint32_t sbase = smem_u32(smem);
    const int tid  = threadIdx.x;
    const int lane = tid & 31;
    const int wid  = tid >> 5;

    float* out_q    = out + 1;
    float* out_perp = out + 1 + (size_t)ntok * DN;
    float* out_idx  = out + 2 + (size_t)ntok * DN;

    float* xs = (float*)(smem + XS_OFF);
    float* bn = (float*)(smem + BN_OFF);
    int*   ka = (int*)(smem + KA_OFF);
    unsigned int* hist = (unsigned int*)(smem + HIST_OFF);
    uint4* cand = (uint4*)(smem + CAND_OFF);

    // ---- once per CTA: convert E to (hi,lo) bf16 SW128 + exact norms + zero hist ----
    for (int idx = tid; idx < KN * DN / 8; idx += NTHREADS) {
        int row = idx >> 3;
        int c8  = (idx & 7) * 8;
        const float* gp = emb + (size_t)row * DN + c8;
        float4 f0 = __ldg((const float4*)gp);
        float4 f1 = __ldg((const float4*)gp + 1);
        uint4 hi, lo; pack8(f0, f1, hi, lo);
        uint32_t off = (uint32_t)row * 128u + (uint32_t)c8 * 2u;
        uint32_t sw  = off ^ ((off >> 3) & 0x70);
        *(uint4*)(smem + BHI_OFF + sw) = hi;
        *(uint4*)(smem + BLO_OFF + sw) = lo;
    }
    for (int k = tid; k < KN; k += NTHREADS) {
        const float* ep = emb + (size_t)k * DN;
        float s = 0.f;
        #pragma unroll
        for (int i = 0; i < DN; i++) s = __fadd_rn(s, __fmul_rn(ep[i], ep[i]));
        bn[k] = s;
    }
    for (int t = tid; t < KN; t += NTHREADS) hist[t] = 0u;
    __syncthreads();

    // per-thread constants for the MMA mapping
    const int wbase = wid * 64;
    const int r8  = lane & 7;
    const int mat = lane >> 3;
    const int c2  = (lane & 3) * 2;

    float bnr[16];
    #pragma unroll
    for (int ni = 0; ni < 8; ni++) {
        bnr[ni * 2]     = bn[wbase + ni * 8 + c2];
        bnr[ni * 2 + 1] = bn[wbase + ni * 8 + c2 + 1];
    }

    double errd = 0.0;
    const int ntile = ntok / TM;

    for (int tile = blockIdx.x; tile < ntile; tile += gridDim.x) {
        const int tok0 = tile * TM;

        // ---- convert X tile + stage f32 ----
        for (int idx = tid; idx < TM * DN / 8; idx += NTHREADS) {
            int row = idx >> 3;
            int c8  = (idx & 7) * 8;
            const float* gp = x + (size_t)(tok0 + row) * DN + c8;
            float4 f0 = __ldg((const float4*)gp);
            float4 f1 = __ldg((const float4*)gp + 1);
            float* xr = xs + row * DN + c8;
            *(float4*)xr = f0; *(float4*)(xr + 4) = f1;
            uint4 hi, lo; pack8(f0, f1, hi, lo);
            uint32_t off = (uint32_t)row * 128u + (uint32_t)c8 * 2u;
            uint32_t sw  = off ^ ((off >> 3) & 0x70);
            *(uint4*)(smem + AHI_OFF + sw) = hi;
            *(uint4*)(smem + ALO_OFF + sw) = lo;
        }
        __syncthreads();

        // ---- MMA: warp owns codes [wid*64, wid*64+64); 8 m-chunks of 16 tokens ----
        #pragma unroll 1
        for (int m = 0; m < 8; m++) {
            float acc[32];
            #pragma unroll
            for (int i = 0; i < 32; i++) acc[i] = 0.f;

            #pragma unroll
            for (int prod = 0; prod < 3; prod++) {
                uint32_t Ab = sbase + (prod == 2 ? ALO_OFF : AHI_OFF);
                uint32_t Bb = sbase + (prod == 1 ? BLO_OFF : BHI_OFF);
                #pragma unroll
                for (int ks = 0; ks < 4; ks++) {
                    uint32_t a[4];
                    {
                        int row = m * 16 + (mat & 1) * 8 + r8;
                        int bc  = ks * 32 + (mat >> 1) * 16;
                        ldsm4(swaddr(Ab, row, bc), a);
                    }
                    uint32_t b[8][2];
                    #pragma unroll
                    for (int q = 0; q < 4; q++) {
                        uint32_t t4[4];
                        int row = wbase + q * 16 + (mat >> 1) * 8 + r8;
                        int bc  = ks * 32 + (mat & 1) * 16;
                        ldsm4(swaddr(Bb, row, bc), t4);
                        b[2*q][0] = t4[0]; b[2*q][1] = t4[1];
                        b[2*q+1][0] = t4[2]; b[2*q+1][1] = t4[3];
                    }
                    #pragma unroll
                    for (int ni = 0; ni < 8; ni++)
                        mma16816(&acc[ni * 4], a, b[ni]);
                }
            }

            // per-token top-2 within this warp's 64 codes
            #pragma unroll
            for (int half = 0; half < 2; half++) {
                float s0 = 3e38f, s1 = 3e38f;
                int   k0 = 0x7fffffff, k1 = 0x7fffffff;
                #pragma unroll
                for (int ni = 0; ni < 8; ni++) {
                    int kk = wbase + ni * 8 + c2;
                    merge2(s0, k0, s1, k1, __fmaf_rn(-2.f, acc[ni*4 + half*2],     bnr[ni*2]),   kk);
                    merge2(s0, k0, s1, k1, __fmaf_rn(-2.f, acc[ni*4 + half*2 + 1], bnr[ni*2+1]), kk + 1);
                }
                #pragma unroll
                for (int off = 1; off <= 2; off <<= 1) {
                    float os0 = __shfl_xor_sync(0xffffffffu, s0, off);
                    int   ok0 = __shfl_xor_sync(0xffffffffu, k0, off);
                    float os1 = __shfl_xor_sync(0xffffffffu, s1, off);
                    int   ok1 = __shfl_xor_sync(0xffffffffu, k1, off);
                    merge2(s0, k0, s1, k1, os0, ok0);
                    merge2(s0, k0, s1, k1, os1, ok1);
                }
                if ((lane & 3) == 0) {
                    int tok = m * 16 + half * 8 + (lane >> 2);
                    cand[tok * 8 + wid] = make_uint4(__float_as_uint(s0), (uint32_t)k0,
                                                     __float_as_uint(s1), (uint32_t)k1);
                }
            }
        }
        __syncthreads();

        // ---- merge top-4 of 16 + exact rescoring (token t = tid < 128) ----
        if (tid < TM) {
            float s[4] = {3e38f, 3e38f, 3e38f, 3e38f};
            int   k[4] = {0x7fffffff, 0x7fffffff, 0x7fffffff, 0x7fffffff};
            #pragma unroll
            for (int w = 0; w < 8; w++) {
                uint4 c = cand[tid * 8 + w];
                ins4(s, k, __uint_as_float(c.x), (int)c.y);
                ins4(s, k, __uint_as_float(c.z), (int)c.w);
            }
            const float* xp = xs + tid * DN;
            float A = 0.f;   // exact reference-order ||x||^2
            #pragma unroll
            for (int i = 0; i < DN; i++) A = __fadd_rn(A, __fmul_rn(xp[i], xp[i]));
            float bd = 3e38f;
            int   bk = 0x7fffffff;
            #pragma unroll
            for (int i = 0; i < 4; i++) {
                float d = exact_d(xp, emb, A, bn[k[i]], k[i]);
                if (d < bd || (d == bd && k[i] < bk)) { bd = d; bk = k[i]; }
            }
            ka[tid] = bk;
            out_idx[tok0 + tid] = (float)bk;
            atomicAdd(&hist[bk], 1u);
        }
        __syncthreads();

        // ---- gather + straight-through write + err sum (8 warps x 16 tokens) ----
        float err = 0.f;
        #pragma unroll 2
        for (int t = wid * 16; t < wid * 16 + 16; t++) {
            int k = ka[t];
            const float* er = emb + (size_t)k * DN;
            const float* xr = xs + t * DN;
            float x0 = xr[lane], x1 = xr[32 + lane];
            float q0 = __ldg(er + lane), q1 = __ldg(er + 32 + lane);
            float d0 = __fsub_rn(q0, x0);
            float d1 = __fsub_rn(q1, x1);
            out_q[(size_t)(tok0 + t) * DN + lane]      = __fadd_rn(x0, d0);
            out_q[(size_t)(tok0 + t) * DN + 32 + lane] = __fadd_rn(x1, d1);
            err = __fmaf_rn(d0, d0, __fmaf_rn(d1, d1, err));
        }
        #pragma unroll
        for (int off = 16; off > 0; off >>= 1)
            err += __shfl_xor_sync(0xffffffffu, err, off);
        errd += (double)err;
        __syncthreads();
    }

    // ---- flush per-CTA accumulators ----
    if (lane == 0) atomicAdd(&g_err_sum, errd);
    for (int t = tid; t < KN; t += NTHREADS) {
        unsigned int c = hist[t];
        if (c) atomicAdd(&g_counts[t], c);
    }
    __threadfence();
    __syncthreads();

    // ---- last CTA: loss + perplexity, then reset state for next graph replay ----
    __shared__ unsigned int s_last;
    __shared__ float s_red[NTHREADS / 32];
    if (tid == 0)
        s_last = (atomicAdd(&g_done, 1u) == (unsigned)(gridDim.x - 1)) ? 1u : 0u;
    __syncthreads();
    if (s_last) {
        float part = 0.f;
        const float invN = 1.0f / (float)ntok;
        for (int k = tid; k < KN; k += NTHREADS) {
            unsigned int c = atomicAdd(&g_counts[k], 0u);   // L2 read
            g_counts[k] = 0u;
            float p = __fmul_rn((float)c, invN);
            part = __fmaf_rn(p, logf(__fadd_rn(p, 1e-10f)), part);
        }
        #pragma unroll
        for (int off = 16; off > 0; off >>= 1)
            part += __shfl_xor_sync(0xffffffffu, part, off);
        if (lane == 0) s_red[wid] = part;
        __syncthreads();
        if (tid == 0) {
            float sum = 0.f;
            #pragma unroll
            for (int w = 0; w < NTHREADS / 32; w++) sum += s_red[w];
            double esum = atomicAdd(&g_err_sum, 0.0);
            float m = (float)(esum / ((double)ntok * (double)DN));
            out[0]      = __fadd_rn(m, __fmul_rn(0.25f, m));
            out_perp[0] = expf(-sum);
            g_err_sum = 0.0;
            g_done = 0u;
        }
    }
}

extern "C" void kernel_launch(void* const* d_in, const int* in_sizes, int n_in,
                              void* d_out, int out_size)
{
    const float* x   = (const float*)d_in[0];
    const float* emb = (const float*)d_in[1];
    const int ntok = in_sizes[0] / DN;   // 65536

    cudaFuncSetAttribute(vq_all, cudaFuncAttributeMaxDynamicSharedMemorySize, SMEM_TOTAL);
    vq_all<<<NBLK, NTHREADS, SMEM_TOTAL>>>(x, emb, (float*)d_out, ntok);
}

// round 5
// speedup vs baseline: 2.9279x; 1.9557x over previous
#include <cuda_runtime.h>
#include <cuda_bf16.h>
#include <cstdint>

// Fused VQ forward: HMMA bf16 3-product split GEMM + exact fp32 rescoring.
// 512 threads (16 warps), persistent grid, branchless IMNMX argmin.
//   inputs [64,1024,64] f32, embedding [512,64] f32
//   out = [loss(1) | quantized_st(65536*64) | perplexity(1) | indices(65536)] f32

#define KN 512
#define DN 64
#define TM 128          // tokens per tile
#define NTHREADS 512
#define NBLK 148

// ---- smem layout (bytes) ----
#define AHI_OFF   0            // [128 x 128B] X hi (SW128)
#define ALO_OFF   16384        // [128 x 128B] X lo
#define BHI_OFF   32768        // [512 x 128B] E hi
#define BLO_OFF   98304        // [512 x 128B] E lo
#define XS_OFF    163840       // [128 x 64] f32 staged X
#define BN_OFF    196608       // [512] f32 ||e||^2
#define KA_OFF    198656       // [128] int chosen code
#define HIST_OFF  199168       // [512] u32 local histogram
#define CAND_OFF  201216       // [128][8] uint2 packed (key1,key2)
#define SMEM_TOTAL 209408

__device__ double       g_err_sum;
__device__ unsigned int g_counts[KN];
__device__ unsigned int g_done;

__device__ __forceinline__ uint32_t smem_u32(const void* p) {
    uint32_t a;
    asm("{ .reg .u64 t; cvta.to.shared.u64 t, %1; cvt.u32.u64 %0, t; }" : "=r"(a) : "l"(p));
    return a;
}
__device__ __forceinline__ void ldsm4(uint32_t addr, uint32_t* r) {
    asm volatile("ldmatrix.sync.aligned.m8n8.x4.shared.b16 {%0,%1,%2,%3}, [%4];"
                 : "=r"(r[0]), "=r"(r[1]), "=r"(r[2]), "=r"(r[3]) : "r"(addr));
}
__device__ __forceinline__ void mma16816(float* d, const uint32_t* a, const uint32_t* b) {
    asm volatile("mma.sync.aligned.m16n8k16.row.col.f32.bf16.bf16.f32 "
                 "{%0,%1,%2,%3}, {%4,%5,%6,%7}, {%8,%9}, {%0,%1,%2,%3};"
                 : "+f"(d[0]), "+f"(d[1]), "+f"(d[2]), "+f"(d[3])
                 : "r"(a[0]), "r"(a[1]), "r"(a[2]), "r"(a[3]), "r"(b[0]), "r"(b[1]));
}
__device__ __forceinline__ uint32_t swaddr(uint32_t base, int row, int bc) {
    return base + row * 128 + (bc ^ ((row & 7) << 4));
}

__device__ __forceinline__ void pack8(const float4 a, const float4 b, uint4& hi, uint4& lo) {
    float f[8] = {a.x, a.y, a.z, a.w, b.x, b.y, b.z, b.w};
    unsigned short h[8], l[8];
    #pragma unroll
    for (int i = 0; i < 8; i++) {
        __nv_bfloat16 hb = __float2bfloat16_rn(f[i]);
        float r = __fsub_rn(f[i], __bfloat162float(hb));
        h[i] = __bfloat16_as_ushort(hb);
        l[i] = __bfloat16_as_ushort(__float2bfloat16_rn(r));
    }
    hi = make_uint4((uint32_t)h[0] | ((uint32_t)h[1] << 16), (uint32_t)h[2] | ((uint32_t)h[3] << 16),
                    (uint32_t)h[4] | ((uint32_t)h[5] << 16), (uint32_t)h[6] | ((uint32_t)h[7] << 16));
    lo = make_uint4((uint32_t)l[0] | ((uint32_t)l[1] << 16), (uint32_t)l[2] | ((uint32_t)l[3] << 16),
                    (uint32_t)l[4] | ((uint32_t)l[5] << 16), (uint32_t)l[6] | ((uint32_t)l[7] << 16));
}

// exact reference-order distance (validated flip-free vs reference)
__device__ __forceinline__ float exact_d(const float* __restrict__ xp,
                                         const float* __restrict__ emb,
                                         float A, float bnk, int k) {
    const float4* ep = (const float4*)(emb + (size_t)k * DN);
    float dot = 0.f;
    #pragma unroll
    for (int i = 0; i < 16; i++) {
        float4 e4 = __ldg(ep + i);
        const float4 x4 = *(const float4*)(xp + 4 * i);
        dot = __fmaf_rn(x4.x, e4.x, dot);
        dot = __fmaf_rn(x4.y, e4.y, dot);
        dot = __fmaf_rn(x4.z, e4.z, dot);
        dot = __fmaf_rn(x4.w, e4.w, dot);
    }
    return __fsub_rn(__fadd_rn(A, bnk), __fmul_rn(2.0f, dot));
}

__global__ void __launch_bounds__(NTHREADS, 1)
vq_all(const float* __restrict__ x, const float* __restrict__ emb,
       float* __restrict__ out, int ntok)
{
    extern __shared__ __align__(1024) char smem[];
    const uint32_t sbase = smem_u32(smem);
    const int tid  = threadIdx.x;
    const int lane = tid & 31;
    const int wid  = tid >> 5;

    float* out_q    = out + 1;
    float* out_perp = out + 1 + (size_t)ntok * DN;
    float* out_idx  = out + 2 + (size_t)ntok * DN;

    float* xs = (float*)(smem + XS_OFF);
    float* bn = (float*)(smem + BN_OFF);
    int*   ka = (int*)(smem + KA_OFF);
    unsigned int* hist = (unsigned int*)(smem + HIST_OFF);
    uint2* cand = (uint2*)(smem + CAND_OFF);

    // ---- once per CTA: convert E to (hi,lo) bf16 SW128 + exact norms + zero hist ----
    for (int idx = tid; idx < KN * DN / 8; idx += NTHREADS) {
        int row = idx >> 3;
        int c8  = (idx & 7) * 8;
        const float* gp = emb + (size_t)row * DN + c8;
        float4 f0 = __ldg((const float4*)gp);
        float4 f1 = __ldg((const float4*)gp + 1);
        uint4 hi, lo; pack8(f0, f1, hi, lo);
        uint32_t off = (uint32_t)row * 128u + (uint32_t)c8 * 2u;
        uint32_t sw  = off ^ ((off >> 3) & 0x70);
        *(uint4*)(smem + BHI_OFF + sw) = hi;
        *(uint4*)(smem + BLO_OFF + sw) = lo;
    }
    for (int k = tid; k < KN; k += NTHREADS) {
        const float* ep = emb + (size_t)k * DN;
        float s = 0.f;
        #pragma unroll
        for (int i = 0; i < DN; i++) s = __fadd_rn(s, __fmul_rn(ep[i], ep[i]));
        bn[k] = s;
    }
    for (int t = tid; t < KN; t += NTHREADS) hist[t] = 0u;
    __syncthreads();

    // per-thread constants: warp (wid&7) owns 64 codes; (wid>>3) picks m-half
    const int wbase = (wid & 7) * 64;
    const int mm0   = (wid >> 3) * 4;
    const int r8  = lane & 7;
    const int mat = lane >> 3;
    const int c2  = (lane & 3) * 2;

    float bnr[16];
    #pragma unroll
    for (int ni = 0; ni < 8; ni++) {
        bnr[ni * 2]     = bn[wbase + ni * 8 + c2];
        bnr[ni * 2 + 1] = bn[wbase + ni * 8 + c2 + 1];
    }

    double errd = 0.0;
    const int ntile = ntok / TM;

    for (int tile = blockIdx.x; tile < ntile; tile += gridDim.x) {
        const int tok0 = tile * TM;

        // ---- convert X tile + stage f32 ----
        for (int idx = tid; idx < TM * DN / 8; idx += NTHREADS) {
            int row = idx >> 3;
            int c8  = (idx & 7) * 8;
            const float* gp = x + (size_t)(tok0 + row) * DN + c8;
            float4 f0 = __ldg((const float4*)gp);
            float4 f1 = __ldg((const float4*)gp + 1);
            float* xr = xs + row * DN + c8;
            *(float4*)xr = f0; *(float4*)(xr + 4) = f1;
            uint4 hi, lo; pack8(f0, f1, hi, lo);
            uint32_t off = (uint32_t)row * 128u + (uint32_t)c8 * 2u;
            uint32_t sw  = off ^ ((off >> 3) & 0x70);
            *(uint4*)(smem + AHI_OFF + sw) = hi;
            *(uint4*)(smem + ALO_OFF + sw) = lo;
        }
        __syncthreads();

        // ---- MMA + branchless top-2: 4 m-chunks of 16 tokens ----
        #pragma unroll 1
        for (int m = 0; m < 4; m++) {
            const int mm = mm0 + m;
            float acc[32];
            #pragma unroll
            for (int i = 0; i < 32; i++) acc[i] = 0.f;

            #pragma unroll
            for (int prod = 0; prod < 3; prod++) {
                uint32_t Ab = sbase + (prod == 2 ? ALO_OFF : AHI_OFF);
                uint32_t Bb = sbase + (prod == 1 ? BLO_OFF : BHI_OFF);
                #pragma unroll
                for (int ks = 0; ks < 4; ks++) {
                    uint32_t a[4];
                    {
                        int row = mm * 16 + (mat & 1) * 8 + r8;
                        int bc  = ks * 32 + (mat >> 1) * 16;
                        ldsm4(swaddr(Ab, row, bc), a);
                    }
                    uint32_t b[8][2];
                    #pragma unroll
                    for (int q = 0; q < 4; q++) {
                        uint32_t t4[4];
                        int row = wbase + q * 16 + (mat >> 1) * 8 + r8;
                        int bc  = ks * 32 + (mat & 1) * 16;
                        ldsm4(swaddr(Bb, row, bc), t4);
                        b[2*q][0] = t4[0]; b[2*q][1] = t4[1];
                        b[2*q+1][0] = t4[2]; b[2*q+1][1] = t4[3];
                    }
                    #pragma unroll
                    for (int ni = 0; ni < 8; ni++)
                        mma16816(&acc[ni * 4], a, b[ni]);
                }
            }

            // per-token top-2 over this warp's 64 codes, packed-key IMNMX
            #pragma unroll
            for (int half = 0; half < 2; half++) {
                uint32_t key[16];
                #pragma unroll
                for (int f = 0; f < 8; f++) {
                    #pragma unroll
                    for (int c = 0; c < 2; c++) {
                        float s = __fmaf_rn(-2.f, acc[f*4 + half*2 + c], bnr[f*2 + c]);
                        float t = __fadd_rn(s, 8.5f);     // t in [8,16): fixed exponent
                        key[f*2 + c] = (__float_as_uint(t) << 9) | (uint32_t)(wbase + f*8 + c2 + c);
                    }
                }
                // min tree (key carries index; low-k wins ties automatically)
                uint32_t t8[8], t4v[4], t2[2];
                #pragma unroll
                for (int i = 0; i < 8; i++) t8[i] = min(key[i], key[i + 8]);
                #pragma unroll
                for (int i = 0; i < 4; i++) t4v[i] = min(t8[i], t8[i + 4]);
                t2[0] = min(t4v[0], t4v[2]); t2[1] = min(t4v[1], t4v[3]);
                uint32_t m1 = min(t2[0], t2[1]);
                m1 = min(m1, __shfl_xor_sync(0xffffffffu, m1, 1));
                m1 = min(m1, __shfl_xor_sync(0xffffffffu, m1, 2));
                // second min: mask the winner, redo
                uint32_t m2 = 0xFFFFFFFFu;
                #pragma unroll
                for (int i = 0; i < 16; i++) {
                    uint32_t u = (key[i] == m1) ? 0xFFFFFFFFu : key[i];
                    m2 = min(m2, u);
                }
                m2 = min(m2, __shfl_xor_sync(0xffffffffu, m2, 1));
                m2 = min(m2, __shfl_xor_sync(0xffffffffu, m2, 2));
                if ((lane & 3) == 0) {
                    int tok = mm * 16 + half * 8 + (lane >> 2);
                    cand[tok * 8 + (wid & 7)] = make_uint2(m1, m2);
                }
            }
        }
        __syncthreads();

        // ---- merge top-4 of 16 packed keys + exact rescoring (token = tid < 128) ----
        if (tid < TM) {
            uint32_t key[16];
            #pragma unroll
            for (int w = 0; w < 8; w++) {
                uint2 c = cand[tid * 8 + w];
                key[w * 2] = c.x; key[w * 2 + 1] = c.y;
            }
            int kc[4];
            #pragma unroll
            for (int p = 0; p < 4; p++) {
                uint32_t t8[8], t4v[4];
                #pragma unroll
                for (int i = 0; i < 8; i++) t8[i] = min(key[i], key[i + 8]);
                #pragma unroll
                for (int i = 0; i < 4; i++) t4v[i] = min(t8[i], t8[i + 4]);
                uint32_t mn = min(min(t4v[0], t4v[1]), min(t4v[2], t4v[3]));
                kc[p] = (int)(mn & 511u);
                #pragma unroll
                for (int i = 0; i < 16; i++)
                    if (key[i] == mn) key[i] = 0xFFFFFFFFu;
            }
            const float* xp = xs + tid * DN;
            float A = 0.f;   // exact reference-order ||x||^2
            #pragma unroll
            for (int i = 0; i < DN; i++) A = __fadd_rn(A, __fmul_rn(xp[i], xp[i]));
            float bd = 3e38f;
            int   bk = 0x7fffffff;
            #pragma unroll
            for (int i = 0; i < 4; i++) {
                float d = exact_d(xp, emb, A, bn[kc[i]], kc[i]);
                if (d < bd || (d == bd && kc[i] < bk)) { bd = d; bk = kc[i]; }
            }
            ka[tid] = bk;
            out_idx[tok0 + tid] = (float)bk;
            atomicAdd(&hist[bk], 1u);
        }
        __syncthreads();

        // ---- gather + straight-through write + err sum (16 warps x 8 tokens) ----
        float err = 0.f;
        #pragma unroll 2
        for (int t = wid * 8; t < wid * 8 + 8; t++) {
            int k = ka[t];
            const float* er = emb + (size_t)k * DN;
            const float* xr = xs + t * DN;
            float x0 = xr[lane], x1 = xr[32 + lane];
            float q0 = __ldg(er + lane), q1 = __ldg(er + 32 + lane);
            float d0 = __fsub_rn(q0, x0);
            float d1 = __fsub_rn(q1, x1);
            out_q[(size_t)(tok0 + t) * DN + lane]      = __fadd_rn(x0, d0);
            out_q[(size_t)(tok0 + t) * DN + 32 + lane] = __fadd_rn(x1, d1);
            err = __fmaf_rn(d0, d0, __fmaf_rn(d1, d1, err));
        }
        #pragma unroll
        for (int off = 16; off > 0; off >>= 1)
            err += __shfl_xor_sync(0xffffffffu, err, off);
        errd += (double)err;
        __syncthreads();
    }

    // ---- flush per-CTA accumulators ----
    if (lane == 0) atomicAdd(&g_err_sum, errd);
    for (int t = tid; t < KN; t += NTHREADS) {
        unsigned int c = hist[t];
        if (c) atomicAdd(&g_counts[t], c);
    }
    __threadfence();
    __syncthreads();

    // ---- last CTA: loss + perplexity, then reset for next graph replay ----
    __shared__ unsigned int s_last;
    __shared__ float s_red[NTHREADS / 32];
    if (tid == 0)
        s_last = (atomicAdd(&g_done, 1u) == (unsigned)(gridDim.x - 1)) ? 1u : 0u;
    __syncthreads();
    if (s_last) {
        float part = 0.f;
        const float invN = 1.0f / (float)ntok;
        for (int k = tid; k < KN; k += NTHREADS) {
            unsigned int c = atomicAdd(&g_counts[k], 0u);
            g_counts[k] = 0u;
            float p = __fmul_rn((float)c, invN);
            part = __fmaf_rn(p, logf(__fadd_rn(p, 1e-10f)), part);
        }
        #pragma unroll
        for (int off = 16; off > 0; off >>= 1)
            part += __shfl_xor_sync(0xffffffffu, part, off);
        if (lane == 0) s_red[wid] = part;
        __syncthreads();
        if (tid == 0) {
            float sum = 0.f;
            #pragma unroll
            for (int w = 0; w < NTHREADS / 32; w++) sum += s_red[w];
            double esum = atomicAdd(&g_err_sum, 0.0);
            float m = (float)(esum / ((double)ntok * (double)DN));
            out[0]      = __fadd_rn(m, __fmul_rn(0.25f, m));
            out_perp[0] = expf(-sum);
            g_err_sum = 0.0;
            g_done = 0u;
        }
    }
}

extern "C" void kernel_launch(void* const* d_in, const int* in_sizes, int n_in,
                              void* d_out, int out_size)
{
    const float* x   = (const float*)d_in[0];
    const float* emb = (const float*)d_in[1];
    const int ntok = in_sizes[0] / DN;   // 65536

    cudaFuncSetAttribute(vq_all, cudaFuncAttributeMaxDynamicSharedMemorySize, SMEM_TOTAL);
    vq_all<<<NBLK, NTHREADS, SMEM_TOTAL>>>(x, emb, (float*)d_out, ntok);
}

// round 6
// speedup vs baseline: 2.9851x; 1.0195x over previous
#include <cuda_runtime.h>
#include <cuda_bf16.h>
#include <cstdint>

// Fused VQ forward: HMMA bf16 3-product split GEMM + exact fp32 rescoring.
// 16 warps; warp owns 32 codes with B-fragments register-cached across all
// 8 m-chunks (cuts LDSM traffic 3x). Branchless IMNMX argmin.
//   inputs [64,1024,64] f32, embedding [512,64] f32
//   out = [loss(1) | quantized_st(65536*64) | perplexity(1) | indices(65536)] f32

#define KN 512
#define DN 64
#define TM 128
#define XSTRIDE 68      // xs row stride in floats (16B-aligned, conflict-free quads)
#define NTHREADS 512
#define NBLK 148

// ---- smem layout (bytes) ----
#define AHI_OFF   0            // [128 x 128B] X hi (SW128)
#define ALO_OFF   16384        // [128 x 128B] X lo
#define BHI_OFF   32768        // [512 x 128B] E hi
#define BLO_OFF   98304        // [512 x 128B] E lo
#define XS_OFF    163840       // [128 x 68] f32 staged X (padded rows)
#define BN_OFF    198656       // [512] f32 ||e||^2
#define KA_OFF    200704       // [128] int chosen code
#define KC_OFF    201216       // [128][4] int candidates
#define HIST_OFF  203264       // [512] u32
#define CAND_OFF  205312       // [16][128] uint2  (warp-major: conflict-free)
#define SMEM_TOTAL 221696

__device__ double       g_err_sum;
__device__ unsigned int g_counts[KN];
__device__ unsigned int g_done;

__device__ __forceinline__ uint32_t smem_u32(const void* p) {
    uint32_t a;
    asm("{ .reg .u64 t; cvta.to.shared.u64 t, %1; cvt.u32.u64 %0, t; }" : "=r"(a) : "l"(p));
    return a;
}
__device__ __forceinline__ void ldsm4(uint32_t addr, uint32_t* r) {
    asm volatile("ldmatrix.sync.aligned.m8n8.x4.shared.b16 {%0,%1,%2,%3}, [%4];"
                 : "=r"(r[0]), "=r"(r[1]), "=r"(r[2]), "=r"(r[3]) : "r"(addr));
}
__device__ __forceinline__ void mma16816(float* d, const uint32_t* a, const uint32_t* b) {
    asm volatile("mma.sync.aligned.m16n8k16.row.col.f32.bf16.bf16.f32 "
                 "{%0,%1,%2,%3}, {%4,%5,%6,%7}, {%8,%9}, {%0,%1,%2,%3};"
                 : "+f"(d[0]), "+f"(d[1]), "+f"(d[2]), "+f"(d[3])
                 : "r"(a[0]), "r"(a[1]), "r"(a[2]), "r"(a[3]), "r"(b[0]), "r"(b[1]));
}
__device__ __forceinline__ uint32_t swaddr(uint32_t base, int row, int bc) {
    return base + row * 128 + (bc ^ ((row & 7) << 4));
}

__device__ __forceinline__ void pack8(const float4 a, const float4 b, uint4& hi, uint4& lo) {
    float f[8] = {a.x, a.y, a.z, a.w, b.x, b.y, b.z, b.w};
    unsigned short h[8], l[8];
    #pragma unroll
    for (int i = 0; i < 8; i++) {
        __nv_bfloat16 hb = __float2bfloat16_rn(f[i]);
        float r = __fsub_rn(f[i], __bfloat162float(hb));
        h[i] = __bfloat16_as_ushort(hb);
        l[i] = __bfloat16_as_ushort(__float2bfloat16_rn(r));
    }
    hi = make_uint4((uint32_t)h[0] | ((uint32_t)h[1] << 16), (uint32_t)h[2] | ((uint32_t)h[3] << 16),
                    (uint32_t)h[4] | ((uint32_t)h[5] << 16), (uint32_t)h[6] | ((uint32_t)h[7] << 16));
    lo = make_uint4((uint32_t)l[0] | ((uint32_t)l[1] << 16), (uint32_t)l[2] | ((uint32_t)l[3] << 16),
                    (uint32_t)l[4] | ((uint32_t)l[5] << 16), (uint32_t)l[6] | ((uint32_t)l[7] << 16));
}

// exact reference-order distance (validated flip-free vs reference)
__device__ __forceinline__ float exact_d(const float* __restrict__ xp,
                                         const float* __restrict__ emb,
                                         float A, float bnk, int k) {
    const float4* ep = (const float4*)(emb + (size_t)k * DN);
    float dot = 0.f;
    #pragma unroll
    for (int i = 0; i < 16; i++) {
        float4 e4 = __ldg(ep + i);
        const float4 x4 = *(const float4*)(xp + 4 * i);
        dot = __fmaf_rn(x4.x, e4.x, dot);
        dot = __fmaf_rn(x4.y, e4.y, dot);
        dot = __fmaf_rn(x4.z, e4.z, dot);
        dot = __fmaf_rn(x4.w, e4.w, dot);
    }
    return __fsub_rn(__fadd_rn(A, bnk), __fmul_rn(2.0f, dot));
}

__global__ void __launch_bounds__(NTHREADS, 1)
vq_all(const float* __restrict__ x, const float* __restrict__ emb,
       float* __restrict__ out, int ntok)
{
    extern __shared__ __align__(1024) char smem[];
    const uint32_t sbase = smem_u32(smem);
    const int tid  = threadIdx.x;
    const int lane = tid & 31;
    const int wid  = tid >> 5;

    float* out_q    = out + 1;
    float* out_perp = out + 1 + (size_t)ntok * DN;
    float* out_idx  = out + 2 + (size_t)ntok * DN;

    float* xs = (float*)(smem + XS_OFF);
    float* bn = (float*)(smem + BN_OFF);
    int*   ka = (int*)(smem + KA_OFF);
    int*   kcs = (int*)(smem + KC_OFF);
    unsigned int* hist = (unsigned int*)(smem + HIST_OFF);
    uint2* cand = (uint2*)(smem + CAND_OFF);   // [16][128]

    // ---- once per CTA: convert E to (hi,lo) bf16 SW128 + exact norms + zero hist ----
    for (int idx = tid; idx < KN * DN / 8; idx += NTHREADS) {
        int row = idx >> 3;
        int c8  = (idx & 7) * 8;
        const float* gp = emb + (size_t)row * DN + c8;
        float4 f0 = __ldg((const float4*)gp);
        float4 f1 = __ldg((const float4*)gp + 1);
        uint4 hi, lo; pack8(f0, f1, hi, lo);
        uint32_t off = (uint32_t)row * 128u + (uint32_t)c8 * 2u;
        uint32_t sw  = off ^ ((off >> 3) & 0x70);
        *(uint4*)(smem + BHI_OFF + sw) = hi;
        *(uint4*)(smem + BLO_OFF + sw) = lo;
    }
    for (int k = tid; k < KN; k += NTHREADS) {
        const float* ep = emb + (size_t)k * DN;
        float s = 0.f;
        #pragma unroll
        for (int i = 0; i < DN; i++) s = __fadd_rn(s, __fmul_rn(ep[i], ep[i]));
        bn[k] = s;
    }
    for (int t = tid; t < KN; t += NTHREADS) hist[t] = 0u;
    __syncthreads();

    // per-thread constants: warp owns 32 codes [wid*32, wid*32+32)
    const int wbase = wid * 32;
    const int r8  = lane & 7;
    const int mat = lane >> 3;
    const int c2  = (lane & 3) * 2;

    float bnr[8];
    #pragma unroll
    for (int nf = 0; nf < 4; nf++) {
        bnr[nf * 2]     = bn[wbase + nf * 8 + c2];
        bnr[nf * 2 + 1] = bn[wbase + nf * 8 + c2 + 1];
    }

    // ---- register-cache B fragments for this warp's 32 codes (per-CTA constant) ----
    uint32_t bh[4][8], bl[4][8];
    #pragma unroll
    for (int ks = 0; ks < 4; ks++) {
        #pragma unroll
        for (int q = 0; q < 2; q++) {
            int row = wbase + q * 16 + (mat >> 1) * 8 + r8;
            int bc  = ks * 32 + (mat & 1) * 16;
            uint32_t t4[4];
            ldsm4(swaddr(sbase + BHI_OFF, row, bc), t4);
            bh[ks][q*4+0] = t4[0]; bh[ks][q*4+1] = t4[1];
            bh[ks][q*4+2] = t4[2]; bh[ks][q*4+3] = t4[3];
            ldsm4(swaddr(sbase + BLO_OFF, row, bc), t4);
            bl[ks][q*4+0] = t4[0]; bl[ks][q*4+1] = t4[1];
            bl[ks][q*4+2] = t4[2]; bl[ks][q*4+3] = t4[3];
        }
    }

    double errd = 0.0;
    const int ntile = ntok / TM;

    for (int tile = blockIdx.x; tile < ntile; tile += gridDim.x) {
        const int tok0 = tile * TM;

        // ---- convert X tile + stage f32 (padded rows) ----
        for (int idx = tid; idx < TM * DN / 8; idx += NTHREADS) {
            int row = idx >> 3;
            int c8  = (idx & 7) * 8;
            const float* gp = x + (size_t)(tok0 + row) * DN + c8;
            float4 f0 = __ldg((const float4*)gp);
            float4 f1 = __ldg((const float4*)gp + 1);
            float* xr = xs + row * XSTRIDE + c8;
            *(float4*)xr = f0; *(float4*)(xr + 4) = f1;
            uint4 hi, lo; pack8(f0, f1, hi, lo);
            uint32_t off = (uint32_t)row * 128u + (uint32_t)c8 * 2u;
            uint32_t sw  = off ^ ((off >> 3) & 0x70);
            *(uint4*)(smem + AHI_OFF + sw) = hi;
            *(uint4*)(smem + ALO_OFF + sw) = lo;
        }
        __syncthreads();

        // ---- MMA: all 8 m-chunks, B in registers, stream A-frags ----
        #pragma unroll 1
        for (int m = 0; m < 8; m++) {
            float acc[16];
            #pragma unroll
            for (int i = 0; i < 16; i++) acc[i] = 0.f;

            #pragma unroll
            for (int ks = 0; ks < 4; ks++) {
                int row = m * 16 + (mat & 1) * 8 + r8;
                int bc  = ks * 32 + (mat >> 1) * 16;
                uint32_t ah[4], al[4];
                ldsm4(swaddr(sbase + AHI_OFF, row, bc), ah);
                ldsm4(swaddr(sbase + ALO_OFF, row, bc), al);
                #pragma unroll
                for (int nf = 0; nf < 4; nf++) mma16816(&acc[nf*4], ah, &bh[ks][nf*2]);
                #pragma unroll
                for (int nf = 0; nf < 4; nf++) mma16816(&acc[nf*4], ah, &bl[ks][nf*2]);
                #pragma unroll
                for (int nf = 0; nf < 4; nf++) mma16816(&acc[nf*4], al, &bh[ks][nf*2]);
            }

            // per-token top-2 over this warp's 32 codes (packed-key IMNMX)
            #pragma unroll
            for (int half = 0; half < 2; half++) {
                uint32_t key[8];
                #pragma unroll
                for (int nf = 0; nf < 4; nf++) {
                    #pragma unroll
                    for (int c = 0; c < 2; c++) {
                        float s = __fmaf_rn(-2.f, acc[nf*4 + half*2 + c], bnr[nf*2 + c]);
                        float t = __fadd_rn(s, 8.5f);   // [8,16): fixed exponent, bit-monotone
                        key[nf*2 + c] = (__float_as_uint(t) << 9) | (uint32_t)(wbase + nf*8 + c2 + c);
                    }
                }
                uint32_t t4[4];
                #pragma unroll
                for (int i = 0; i < 4; i++) t4[i] = min(key[i], key[i + 4]);
                uint32_t m1 = min(min(t4[0], t4[2]), min(t4[1], t4[3]));
                m1 = min(m1, __shfl_xor_sync(0xffffffffu, m1, 1));
                m1 = min(m1, __shfl_xor_sync(0xffffffffu, m1, 2));
                uint32_t m2 = 0xFFFFFFFFu;
                #pragma unroll
                for (int i = 0; i < 8; i++) {
                    uint32_t u = (key[i] == m1) ? 0xFFFFFFFFu : key[i];
                    m2 = min(m2, u);
                }
                m2 = min(m2, __shfl_xor_sync(0xffffffffu, m2, 1));
                m2 = min(m2, __shfl_xor_sync(0xffffffffu, m2, 2));
                if ((lane & 3) == 0) {
                    int tok = m * 16 + half * 8 + (lane >> 2);
                    cand[wid * 128 + tok] = make_uint2(m1, m2);  // warp-major: conflict-free
                }
            }
        }
        __syncthreads();

        // ---- merge top-4 of 32 packed keys (token = tid < 128) ----
        if (tid < TM) {
            uint32_t key[32];
            #pragma unroll
            for (int w = 0; w < 16; w++) {
                uint2 c = cand[w * 128 + tid];
                key[w * 2] = c.x; key[w * 2 + 1] = c.y;
            }
            #pragma unroll
            for (int p = 0; p < 4; p++) {
                uint32_t t16[16];
                #pragma unroll
                for (int i = 0; i < 16; i++) t16[i] = min(key[i], key[i + 16]);
                #pragma unroll
                for (int i = 0; i < 8; i++) t16[i] = min(t16[i], t16[i + 8]);
                #pragma unroll
                for (int i = 0; i < 4; i++) t16[i] = min(t16[i], t16[i + 4]);
                uint32_t mn = min(min(t16[0], t16[1]), min(t16[2], t16[3]));
                kcs[tid * 4 + p] = (int)(mn & 511u);
                #pragma unroll
                for (int i = 0; i < 32; i++)
                    if (key[i] == mn) key[i] = 0xFFFFFFFFu;
            }
        }
        __syncthreads();

        // ---- exact rescoring: 4 threads per token, one candidate each ----
        {
            const int tok = tid >> 2;
            const int ci  = tid & 3;
            const int kc  = kcs[tok * 4 + ci];
            const float* xp = xs + tok * XSTRIDE;
            float A = 0.f;   // exact reference-order ||x||^2
            #pragma unroll
            for (int i = 0; i < DN; i++) A = __fadd_rn(A, __fmul_rn(xp[i], xp[i]));
            float bd = exact_d(xp, emb, A, bn[kc], kc);
            int   bk = kc;
            #pragma unroll
            for (int off = 1; off <= 2; off <<= 1) {
                float od = __shfl_xor_sync(0xffffffffu, bd, off);
                int   ok = __shfl_xor_sync(0xffffffffu, bk, off);
                if (od < bd || (od == bd && ok < bk)) { bd = od; bk = ok; }
            }
            if (ci == 0) {
                ka[tok] = bk;
                out_idx[tok0 + tok] = (float)bk;
                atomicAdd(&hist[bk], 1u);
            }
        }
        __syncthreads();

        // ---- gather + straight-through write + err sum (16 warps x 8 tokens) ----
        float err = 0.f;
        #pragma unroll 2
        for (int t = wid * 8; t < wid * 8 + 8; t++) {
            int k = ka[t];
            const float* er = emb + (size_t)k * DN;
            const float* xr = xs + t * XSTRIDE;
            float x0 = xr[lane], x1 = xr[32 + lane];
            float q0 = __ldg(er + lane), q1 = __ldg(er + 32 + lane);
            float d0 = __fsub_rn(q0, x0);
            float d1 = __fsub_rn(q1, x1);
            out_q[(size_t)(tok0 + t) * DN + lane]      = __fadd_rn(x0, d0);
            out_q[(size_t)(tok0 + t) * DN + 32 + lane] = __fadd_rn(x1, d1);
            err = __fmaf_rn(d0, d0, __fmaf_rn(d1, d1, err));
        }
        #pragma unroll
        for (int off = 16; off > 0; off >>= 1)
            err += __shfl_xor_sync(0xffffffffu, err, off);
        errd += (double)err;
        __syncthreads();
    }

    // ---- flush per-CTA accumulators ----
    if (lane == 0) atomicAdd(&g_err_sum, errd);
    for (int t = tid; t < KN; t += NTHREADS) {
        unsigned int c = hist[t];
        if (c) atomicAdd(&g_counts[t], c);
    }
    __threadfence();
    __syncthreads();

    // ---- last CTA: loss + perplexity, then reset for next graph replay ----
    __shared__ unsigned int s_last;
    __shared__ float s_red[NTHREADS / 32];
    if (tid == 0)
        s_last = (atomicAdd(&g_done, 1u) == (unsigned)(gridDim.x - 1)) ? 1u : 0u;
    __syncthreads();
    if (s_last) {
        float part = 0.f;
        const float invN = 1.0f / (float)ntok;
        for (int k = tid; k < KN; k += NTHREADS) {
            unsigned int c = atomicAdd(&g_counts[k], 0u);
            g_counts[k] = 0u;
            float p = __fmul_rn((float)c, invN);
            part = __fmaf_rn(p, logf(__fadd_rn(p, 1e-10f)), part);
        }
        #pragma unroll
        for (int off = 16; off > 0; off >>= 1)
            part += __shfl_xor_sync(0xffffffffu, part, off);
        if (lane == 0) s_red[wid] = part;
        __syncthreads();
        if (tid == 0) {
            float sum = 0.f;
            #pragma unroll
            for (int w = 0; w < NTHREADS / 32; w++) sum += s_red[w];
            double esum = atomicAdd(&g_err_sum, 0.0);
            float m = (float)(esum / ((double)ntok * (double)DN));
            out[0]      = __fadd_rn(m, __fmul_rn(0.25f, m));
            out_perp[0] = expf(-sum);
            g_err_sum = 0.0;
            g_done = 0u;
        }
    }
}

extern "C" void kernel_launch(void* const* d_in, const int* in_sizes, int n_in,
                              void* d_out, int out_size)
{
    const float* x   = (const float*)d_in[0];
    const float* emb = (const float*)d_in[1];
    const int ntok = in_sizes[0] / DN;   // 65536

    cudaFuncSetAttribute(vq_all, cudaFuncAttributeMaxDynamicSharedMemorySize, SMEM_TOTAL);
    vq_all<<<NBLK, NTHREADS, SMEM_TOTAL>>>(x, emb, (float*)d_out, ntok);
}

// round 7
// speedup vs baseline: 3.0044x; 1.0065x over previous
#include <cuda_runtime.h>
#include <cuda_bf16.h>
#include <cstdint>

// Fused VQ forward: HMMA bf16 3-product split GEMM + exact fp32 rescoring.
// 16 warps; warp owns 32 codes with B-fragments register-cached across all
// 8 m-chunks (cuts LDSM traffic 3x). Branchless IMNMX argmin.
//   inputs [64,1024,64] f32, embedding [512,64] f32
//   out = [loss(1) | quantized_st(65536*64) | perplexity(1) | indices(65536)] f32

#define KN 512
#define DN 64
#define TM 128
#define XSTRIDE 68      // xs row stride in floats (16B-aligned, conflict-free quads)
#define NTHREADS 512
#define NBLK 148

// ---- smem layout (bytes) ----
#define AHI_OFF   0            // [128 x 128B] X hi (SW128)
#define ALO_OFF   16384        // [128 x 128B] X lo
#define BHI_OFF   32768        // [512 x 128B] E hi
#define BLO_OFF   98304        // [512 x 128B] E lo
#define XS_OFF    163840       // [128 x 68] f32 staged X (padded rows)
#define BN_OFF    198656       // [512] f32 ||e||^2
#define KA_OFF    200704       // [128] int chosen code
#define KC_OFF    201216       // [128][4] int candidates
#define HIST_OFF  203264       // [512] u32
#define CAND_OFF  205312       // [16][128] uint2  (warp-major: conflict-free)
#define SMEM_TOTAL 221696

__device__ double       g_err_sum;
__device__ unsigned int g_counts[KN];
__device__ unsigned int g_done;

__device__ __forceinline__ uint32_t smem_u32(const void* p) {
    uint32_t a;
    asm("{ .reg .u64 t; cvta.to.shared.u64 t, %1; cvt.u32.u64 %0, t; }" : "=r"(a) : "l"(p));
    return a;
}
__device__ __forceinline__ void ldsm4(uint32_t addr, uint32_t* r) {
    asm volatile("ldmatrix.sync.aligned.m8n8.x4.shared.b16 {%0,%1,%2,%3}, [%4];"
                 : "=r"(r[0]), "=r"(r[1]), "=r"(r[2]), "=r"(r[3]) : "r"(addr));
}
__device__ __forceinline__ void mma16816(float* d, const uint32_t* a, const uint32_t* b) {
    asm volatile("mma.sync.aligned.m16n8k16.row.col.f32.bf16.bf16.f32 "
                 "{%0,%1,%2,%3}, {%4,%5,%6,%7}, {%8,%9}, {%0,%1,%2,%3};"
                 : "+f"(d[0]), "+f"(d[1]), "+f"(d[2]), "+f"(d[3])
                 : "r"(a[0]), "r"(a[1]), "r"(a[2]), "r"(a[3]), "r"(b[0]), "r"(b[1]));
}
__device__ __forceinline__ uint32_t swaddr(uint32_t base, int row, int bc) {
    return base + row * 128 + (bc ^ ((row & 7) << 4));
}

__device__ __forceinline__ void pack8(const float4 a, const float4 b, uint4& hi, uint4& lo) {
    float f[8] = {a.x, a.y, a.z, a.w, b.x, b.y, b.z, b.w};
    unsigned short h[8], l[8];
    #pragma unroll
    for (int i = 0; i < 8; i++) {
        __nv_bfloat16 hb = __float2bfloat16_rn(f[i]);
        float r = __fsub_rn(f[i], __bfloat162float(hb));
        h[i] = __bfloat16_as_ushort(hb);
        l[i] = __bfloat16_as_ushort(__float2bfloat16_rn(r));
    }
    hi = make_uint4((uint32_t)h[0] | ((uint32_t)h[1] << 16), (uint32_t)h[2] | ((uint32_t)h[3] << 16),
                    (uint32_t)h[4] | ((uint32_t)h[5] << 16), (uint32_t)h[6] | ((uint32_t)h[7] << 16));
    lo = make_uint4((uint32_t)l[0] | ((uint32_t)l[1] << 16), (uint32_t)l[2] | ((uint32_t)l[3] << 16),
                    (uint32_t)l[4] | ((uint32_t)l[5] << 16), (uint32_t)l[6] | ((uint32_t)l[7] << 16));
}

// exact reference-order distance (validated flip-free vs reference)
__device__ __forceinline__ float exact_d(const float* __restrict__ xp,
                                         const float* __restrict__ emb,
                                         float A, float bnk, int k) {
    const float4* ep = (const float4*)(emb + (size_t)k * DN);
    float dot = 0.f;
    #pragma unroll
    for (int i = 0; i < 16; i++) {
        float4 e4 = __ldg(ep + i);
        const float4 x4 = *(const float4*)(xp + 4 * i);
        dot = __fmaf_rn(x4.x, e4.x, dot);
        dot = __fmaf_rn(x4.y, e4.y, dot);
        dot = __fmaf_rn(x4.z, e4.z, dot);
        dot = __fmaf_rn(x4.w, e4.w, dot);
    }
    return __fsub_rn(__fadd_rn(A, bnk), __fmul_rn(2.0f, dot));
}

__global__ void __launch_bounds__(NTHREADS, 1)
vq_all(const float* __restrict__ x, const float* __restrict__ emb,
       float* __restrict__ out, int ntok)
{
    extern __shared__ __align__(1024) char smem[];
    const uint32_t sbase = smem_u32(smem);
    const int tid  = threadIdx.x;
    const int lane = tid & 31;
    const int wid  = tid >> 5;

    float* out_q    = out + 1;
    float* out_perp = out + 1 + (size_t)ntok * DN;
    float* out_idx  = out + 2 + (size_t)ntok * DN;

    float* xs = (float*)(smem + XS_OFF);
    float* bn = (float*)(smem + BN_OFF);
    int*   ka = (int*)(smem + KA_OFF);
    int*   kcs = (int*)(smem + KC_OFF);
    unsigned int* hist = (unsigned int*)(smem + HIST_OFF);
    uint2* cand = (uint2*)(smem + CAND_OFF);   // [16][128]

    // ---- once per CTA: convert E to (hi,lo) bf16 SW128 + exact norms + zero hist ----
    for (int idx = tid; idx < KN * DN / 8; idx += NTHREADS) {
        int row = idx >> 3;
        int c8  = (idx & 7) * 8;
        const float* gp = emb + (size_t)row * DN + c8;
        float4 f0 = __ldg((const float4*)gp);
        float4 f1 = __ldg((const float4*)gp + 1);
        uint4 hi, lo; pack8(f0, f1, hi, lo);
        uint32_t off = (uint32_t)row * 128u + (uint32_t)c8 * 2u;
        uint32_t sw  = off ^ ((off >> 3) & 0x70);
        *(uint4*)(smem + BHI_OFF + sw) = hi;
        *(uint4*)(smem + BLO_OFF + sw) = lo;
    }
    for (int k = tid; k < KN; k += NTHREADS) {
        const float* ep = emb + (size_t)k * DN;
        float s = 0.f;
        #pragma unroll
        for (int i = 0; i < DN; i++) s = __fadd_rn(s, __fmul_rn(ep[i], ep[i]));
        bn[k] = s;
    }
    for (int t = tid; t < KN; t += NTHREADS) hist[t] = 0u;
    __syncthreads();

    // per-thread constants: warp owns 32 codes [wid*32, wid*32+32)
    const int wbase = wid * 32;
    const int r8  = lane & 7;
    const int mat = lane >> 3;
    const int c2  = (lane & 3) * 2;

    float bnr[8];
    #pragma unroll
    for (int nf = 0; nf < 4; nf++) {
        bnr[nf * 2]     = bn[wbase + nf * 8 + c2];
        bnr[nf * 2 + 1] = bn[wbase + nf * 8 + c2 + 1];
    }

    // ---- register-cache B fragments for this warp's 32 codes (per-CTA constant) ----
    uint32_t bh[4][8], bl[4][8];
    #pragma unroll
    for (int ks = 0; ks < 4; ks++) {
        #pragma unroll
        for (int q = 0; q < 2; q++) {
            int row = wbase + q * 16 + (mat >> 1) * 8 + r8;
            int bc  = ks * 32 + (mat & 1) * 16;
            uint32_t t4[4];
            ldsm4(swaddr(sbase + BHI_OFF, row, bc), t4);
            bh[ks][q*4+0] = t4[0]; bh[ks][q*4+1] = t4[1];
            bh[ks][q*4+2] = t4[2]; bh[ks][q*4+3] = t4[3];
            ldsm4(swaddr(sbase + BLO_OFF, row, bc), t4);
            bl[ks][q*4+0] = t4[0]; bl[ks][q*4+1] = t4[1];
            bl[ks][q*4+2] = t4[2]; bl[ks][q*4+3] = t4[3];
        }
    }

    double errd = 0.0;
    const int ntile = ntok / TM;

    for (int tile = blockIdx.x; tile < ntile; tile += gridDim.x) {
        const int tok0 = tile * TM;

        // ---- convert X tile + stage f32 (padded rows) ----
        for (int idx = tid; idx < TM * DN / 8; idx += NTHREADS) {
            int row = idx >> 3;
            int c8  = (idx & 7) * 8;
            const float* gp = x + (size_t)(tok0 + row) * DN + c8;
            float4 f0 = __ldg((const float4*)gp);
            float4 f1 = __ldg((const float4*)gp + 1);
            float* xr = xs + row * XSTRIDE + c8;
            *(float4*)xr = f0; *(float4*)(xr + 4) = f1;
            uint4 hi, lo; pack8(f0, f1, hi, lo);
            uint32_t off = (uint32_t)row * 128u + (uint32_t)c8 * 2u;
            uint32_t sw  = off ^ ((off >> 3) & 0x70);
            *(uint4*)(smem + AHI_OFF + sw) = hi;
            *(uint4*)(smem + ALO_OFF + sw) = lo;
        }
        __syncthreads();

        // ---- MMA: all 8 m-chunks, B in registers, stream A-frags ----
        #pragma unroll 1
        for (int m = 0; m < 8; m++) {
            float acc[16];
            #pragma unroll
            for (int i = 0; i < 16; i++) acc[i] = 0.f;

            #pragma unroll
            for (int ks = 0; ks < 4; ks++) {
                int row = m * 16 + (mat & 1) * 8 + r8;
                int bc  = ks * 32 + (mat >> 1) * 16;
                uint32_t ah[4], al[4];
                ldsm4(swaddr(sbase + AHI_OFF, row, bc), ah);
                ldsm4(swaddr(sbase + ALO_OFF, row, bc), al);
                #pragma unroll
                for (int nf = 0; nf < 4; nf++) mma16816(&acc[nf*4], ah, &bh[ks][nf*2]);
                #pragma unroll
                for (int nf = 0; nf < 4; nf++) mma16816(&acc[nf*4], ah, &bl[ks][nf*2]);
                #pragma unroll
                for (int nf = 0; nf < 4; nf++) mma16816(&acc[nf*4], al, &bh[ks][nf*2]);
            }

            // per-token top-2 over this warp's 32 codes (packed-key IMNMX)
            #pragma unroll
            for (int half = 0; half < 2; half++) {
                uint32_t key[8];
                #pragma unroll
                for (int nf = 0; nf < 4; nf++) {
                    #pragma unroll
                    for (int c = 0; c < 2; c++) {
                        float s = __fmaf_rn(-2.f, acc[nf*4 + half*2 + c], bnr[nf*2 + c]);
                        float t = __fadd_rn(s, 8.5f);   // [8,16): fixed exponent, bit-monotone
                        key[nf*2 + c] = (__float_as_uint(t) << 9) | (uint32_t)(wbase + nf*8 + c2 + c);
                    }
                }
                uint32_t t4[4];
                #pragma unroll
                for (int i = 0; i < 4; i++) t4[i] = min(key[i], key[i + 4]);
                uint32_t m1 = min(min(t4[0], t4[2]), min(t4[1], t4[3]));
                m1 = min(m1, __shfl_xor_sync(0xffffffffu, m1, 1));
                m1 = min(m1, __shfl_xor_sync(0xffffffffu, m1, 2));
                uint32_t m2 = 0xFFFFFFFFu;
                #pragma unroll
                for (int i = 0; i < 8; i++) {
                    uint32_t u = (key[i] == m1) ? 0xFFFFFFFFu : key[i];
                    m2 = min(m2, u);
                }
                m2 = min(m2, __shfl_xor_sync(0xffffffffu, m2, 1));
                m2 = min(m2, __shfl_xor_sync(0xffffffffu, m2, 2));
                if ((lane & 3) == 0) {
                    int tok = m * 16 + half * 8 + (lane >> 2);
                    cand[wid * 128 + tok] = make_uint2(m1, m2);  // warp-major: conflict-free
                }
            }
        }
        __syncthreads();

        // ---- merge top-4 of 32 packed keys (token = tid < 128) ----
        if (tid < TM) {
            uint32_t key[32];
            #pragma unroll
            for (int w = 0; w < 16; w++) {
                uint2 c = cand[w * 128 + tid];
                key[w * 2] = c.x; key[w * 2 + 1] = c.y;
            }
            #pragma unroll
            for (int p = 0; p < 4; p++) {
                uint32_t t16[16];
                #pragma unroll
                for (int i = 0; i < 16; i++) t16[i] = min(key[i], key[i + 16]);
                #pragma unroll
                for (int i = 0; i < 8; i++) t16[i] = min(t16[i], t16[i + 8]);
                #pragma unroll
                for (int i = 0; i < 4; i++) t16[i] = min(t16[i], t16[i + 4]);
                uint32_t mn = min(min(t16[0], t16[1]), min(t16[2], t16[3]));
                kcs[tid * 4 + p] = (int)(mn & 511u);
                #pragma unroll
                for (int i = 0; i < 32; i++)
                    if (key[i] == mn) key[i] = 0xFFFFFFFFu;
            }
        }
        __syncthreads();

        // ---- exact rescoring: 4 threads per token, one candidate each ----
        {
            const int tok = tid >> 2;
            const int ci  = tid & 3;
            const int kc  = kcs[tok * 4 + ci];
            const float* xp = xs + tok * XSTRIDE;
            float A = 0.f;   // exact reference-order ||x||^2
            #pragma unroll
            for (int i = 0; i < DN; i++) A = __fadd_rn(A, __fmul_rn(xp[i], xp[i]));
            float bd = exact_d(xp, emb, A, bn[kc], kc);
            int   bk = kc;
            #pragma unroll
            for (int off = 1; off <= 2; off <<= 1) {
                float od = __shfl_xor_sync(0xffffffffu, bd, off);
                int   ok = __shfl_xor_sync(0xffffffffu, bk, off);
                if (od < bd || (od == bd && ok < bk)) { bd = od; bk = ok; }
            }
            if (ci == 0) {
                ka[tok] = bk;
                out_idx[tok0 + tok] = (float)bk;
                atomicAdd(&hist[bk], 1u);
            }
        }
        __syncthreads();

        // ---- gather + straight-through write + err sum (16 warps x 8 tokens) ----
        float err = 0.f;
        #pragma unroll 2
        for (int t = wid * 8; t < wid * 8 + 8; t++) {
            int k = ka[t];
            const float* er = emb + (size_t)k * DN;
            const float* xr = xs + t * XSTRIDE;
            float x0 = xr[lane], x1 = xr[32 + lane];
            float q0 = __ldg(er + lane), q1 = __ldg(er + 32 + lane);
            float d0 = __fsub_rn(q0, x0);
            float d1 = __fsub_rn(q1, x1);
            out_q[(size_t)(tok0 + t) * DN + lane]      = __fadd_rn(x0, d0);
            out_q[(size_t)(tok0 + t) * DN + 32 + lane] = __fadd_rn(x1, d1);
            err = __fmaf_rn(d0, d0, __fmaf_rn(d1, d1, err));
        }
        #pragma unroll
        for (int off = 16; off > 0; off >>= 1)
            err += __shfl_xor_sync(0xffffffffu, err, off);
        errd += (double)err;
        __syncthreads();
    }

    // ---- flush per-CTA accumulators ----
    if (lane == 0) atomicAdd(&g_err_sum, errd);
    for (int t = tid; t < KN; t += NTHREADS) {
        unsigned int c = hist[t];
        if (c) atomicAdd(&g_counts[t], c);
    }
    __threadfence();
    __syncthreads();

    // ---- last CTA: loss + perplexity, then reset for next graph replay ----
    __shared__ unsigned int s_last;
    __shared__ float s_red[NTHREADS / 32];
    if (tid == 0)
        s_last = (atomicAdd(&g_done, 1u) == (unsigned)(gridDim.x - 1)) ? 1u : 0u;
    __syncthreads();
    if (s_last) {
        float part = 0.f;
        const float invN = 1.0f / (float)ntok;
        for (int k = tid; k < KN; k += NTHREADS) {
            unsigned int c = atomicAdd(&g_counts[k], 0u);
            g_counts[k] = 0u;
            float p = __fmul_rn((float)c, invN);
            part = __fmaf_rn(p, logf(__fadd_rn(p, 1e-10f)), part);
        }
        #pragma unroll
        for (int off = 16; off > 0; off >>= 1)
            part += __shfl_xor_sync(0xffffffffu, part, off);
        if (lane == 0) s_red[wid] = part;
        __syncthreads();
        if (tid == 0) {
            float sum = 0.f;
            #pragma unroll
            for (int w = 0; w < NTHREADS / 32; w++) sum += s_red[w];
            double esum = atomicAdd(&g_err_sum, 0.0);
            float m = (float)(esum / ((double)ntok * (double)DN));
            out[0]      = __fadd_rn(m, __fmul_rn(0.25f, m));
            out_perp[0] = expf(-sum);
            g_err_sum = 0.0;
            g_done = 0u;
        }
    }
}

extern "C" void kernel_launch(void* const* d_in, const int* in_sizes, int n_in,
                              void* d_out, int out_size)
{
    const float* x   = (const float*)d_in[0];
    const float* emb = (const float*)d_in[1];
    const int ntok = in_sizes[0] / DN;   // 65536

    cudaFuncSetAttribute(vq_all, cudaFuncAttributeMaxDynamicSharedMemorySize, SMEM_TOTAL);
    vq_all<<<NBLK, NTHREADS, SMEM_TOTAL>>>(x, emb, (float*)d_out, ntok);
}

// round 8
// speedup vs baseline: 4.5554x; 1.5162x over previous
#include <cuda_runtime.h>
#include <cuda_fp16.h>
#include <cstdint>

// Fused VQ forward: single-product fp16 HMMA GEMM + exact fp32 top-4 rescoring.
// 16 warps; warp owns 32 codes, B register-cached. Pair-propagating IMNMX top-2.
//   inputs [64,1024,64] f32, embedding [512,64] f32
//   out = [loss(1) | quantized_st(65536*64) | perplexity(1) | indices(65536)] f32

#define KN 512
#define DN 64
#define TM 128
#define XSTRIDE 68
#define NTHREADS 512
#define NBLK 148

// ---- smem layout (bytes) ----
#define AH_OFF    0            // [128 x 128B] X fp16 (SW128)
#define BH_OFF    16384        // [512 x 128B] E fp16 (SW128)
#define XS_OFF    81920        // [128 x 68] f32 staged X
#define BN_OFF    116736       // [512] f32 ||e||^2
#define KA_OFF    118784       // [128] int chosen code
#define KC_OFF    119296       // [128][4] int candidates
#define HIST_OFF  121344       // [512] u32
#define CAND_OFF  123392       // [16][128] uint2
#define SMEM_TOTAL 139776

__device__ double       g_err_sum;
__device__ unsigned int g_counts[KN];
__device__ unsigned int g_done;

__device__ __forceinline__ uint32_t smem_u32(const void* p) {
    uint32_t a;
    asm("{ .reg .u64 t; cvta.to.shared.u64 t, %1; cvt.u32.u64 %0, t; }" : "=r"(a) : "l"(p));
    return a;
}
__device__ __forceinline__ void ldsm4(uint32_t addr, uint32_t* r) {
    asm volatile("ldmatrix.sync.aligned.m8n8.x4.shared.b16 {%0,%1,%2,%3}, [%4];"
                 : "=r"(r[0]), "=r"(r[1]), "=r"(r[2]), "=r"(r[3]) : "r"(addr));
}
__device__ __forceinline__ void mma16816(float* d, const uint32_t* a, const uint32_t* b) {
    asm volatile("mma.sync.aligned.m16n8k16.row.col.f32.f16.f16.f32 "
                 "{%0,%1,%2,%3}, {%4,%5,%6,%7}, {%8,%9}, {%0,%1,%2,%3};"
                 : "+f"(d[0]), "+f"(d[1]), "+f"(d[2]), "+f"(d[3])
                 : "r"(a[0]), "r"(a[1]), "r"(a[2]), "r"(a[3]), "r"(b[0]), "r"(b[1]));
}
__device__ __forceinline__ uint32_t swaddr(uint32_t base, int row, int bc) {
    return base + row * 128 + (bc ^ ((row & 7) << 4));
}

// pack 8 consecutive floats -> 8 fp16 (4 x fp16x2 regs)
__device__ __forceinline__ uint4 pack8h(const float4 a, const float4 b) {
    __half2 h0 = __floats2half2_rn(a.x, a.y);
    __half2 h1 = __floats2half2_rn(a.z, a.w);
    __half2 h2 = __floats2half2_rn(b.x, b.y);
    __half2 h3 = __floats2half2_rn(b.z, b.w);
    uint4 r;
    r.x = *reinterpret_cast<uint32_t*>(&h0);
    r.y = *reinterpret_cast<uint32_t*>(&h1);
    r.z = *reinterpret_cast<uint32_t*>(&h2);
    r.w = *reinterpret_cast<uint32_t*>(&h3);
    return r;
}

// exact reference-order distance (validated flip-free vs reference)
__device__ __forceinline__ float exact_d(const float* __restrict__ xp,
                                         const float* __restrict__ emb,
                                         float A, float bnk, int k) {
    const float4* ep = (const float4*)(emb + (size_t)k * DN);
    float dot = 0.f;
    #pragma unroll
    for (int i = 0; i < 16; i++) {
        float4 e4 = __ldg(ep + i);
        const float4 x4 = *(const float4*)(xp + 4 * i);
        dot = __fmaf_rn(x4.x, e4.x, dot);
        dot = __fmaf_rn(x4.y, e4.y, dot);
        dot = __fmaf_rn(x4.z, e4.z, dot);
        dot = __fmaf_rn(x4.w, e4.w, dot);
    }
    return __fsub_rn(__fadd_rn(A, bnk), __fmul_rn(2.0f, dot));
}

__global__ void __launch_bounds__(NTHREADS, 1)
vq_all(const float* __restrict__ x, const float* __restrict__ emb,
       float* __restrict__ out, int ntok)
{
    extern __shared__ __align__(1024) char smem[];
    const uint32_t sbase = smem_u32(smem);
    const int tid  = threadIdx.x;
    const int lane = tid & 31;
    const int wid  = tid >> 5;

    float* out_q    = out + 1;
    float* out_perp = out + 1 + (size_t)ntok * DN;
    float* out_idx  = out + 2 + (size_t)ntok * DN;

    float* xs = (float*)(smem + XS_OFF);
    float* bn = (float*)(smem + BN_OFF);
    int*   ka = (int*)(smem + KA_OFF);
    int*   kcs = (int*)(smem + KC_OFF);
    unsigned int* hist = (unsigned int*)(smem + HIST_OFF);
    uint2* cand = (uint2*)(smem + CAND_OFF);   // [16][128]

    // ---- once per CTA: convert E to fp16 SW128 + exact norms + zero hist ----
    for (int idx = tid; idx < KN * DN / 8; idx += NTHREADS) {
        int row = idx >> 3;
        int c8  = (idx & 7) * 8;
        const float* gp = emb + (size_t)row * DN + c8;
        float4 f0 = __ldg((const float4*)gp);
        float4 f1 = __ldg((const float4*)gp + 1);
        uint32_t off = (uint32_t)row * 128u + (uint32_t)c8 * 2u;
        uint32_t sw  = off ^ ((off >> 3) & 0x70);
        *(uint4*)(smem + BH_OFF + sw) = pack8h(f0, f1);
    }
    for (int k = tid; k < KN; k += NTHREADS) {
        const float* ep = emb + (size_t)k * DN;
        float s = 0.f;
        #pragma unroll
        for (int i = 0; i < DN; i++) s = __fadd_rn(s, __fmul_rn(ep[i], ep[i]));
        bn[k] = s;
    }
    for (int t = tid; t < KN; t += NTHREADS) hist[t] = 0u;
    __syncthreads();

    // per-thread constants: warp owns 32 codes [wid*32, wid*32+32)
    const int wbase = wid * 32;
    const int r8  = lane & 7;
    const int mat = lane >> 3;
    const int c2  = (lane & 3) * 2;

    float bnr[8];
    #pragma unroll
    for (int nf = 0; nf < 4; nf++) {
        bnr[nf * 2]     = bn[wbase + nf * 8 + c2];
        bnr[nf * 2 + 1] = bn[wbase + nf * 8 + c2 + 1];
    }

    // ---- register-cache B fragments (fp16) for this warp's 32 codes ----
    uint32_t bh[4][8];
    #pragma unroll
    for (int ks = 0; ks < 4; ks++) {
        #pragma unroll
        for (int q = 0; q < 2; q++) {
            int row = wbase + q * 16 + (mat >> 1) * 8 + r8;
            int bc  = ks * 32 + (mat & 1) * 16;
            uint32_t t4[4];
            ldsm4(swaddr(sbase + BH_OFF, row, bc), t4);
            bh[ks][q*4+0] = t4[0]; bh[ks][q*4+1] = t4[1];
            bh[ks][q*4+2] = t4[2]; bh[ks][q*4+3] = t4[3];
        }
    }

    double errd = 0.0;
    const int ntile = ntok / TM;

    for (int tile = blockIdx.x; tile < ntile; tile += gridDim.x) {
        const int tok0 = tile * TM;

        // ---- convert X tile to fp16 + stage f32 ----
        for (int idx = tid; idx < TM * DN / 8; idx += NTHREADS) {
            int row = idx >> 3;
            int c8  = (idx & 7) * 8;
            const float* gp = x + (size_t)(tok0 + row) * DN + c8;
            float4 f0 = __ldg((const float4*)gp);
            float4 f1 = __ldg((const float4*)gp + 1);
            float* xr = xs + row * XSTRIDE + c8;
            *(float4*)xr = f0; *(float4*)(xr + 4) = f1;
            uint32_t off = (uint32_t)row * 128u + (uint32_t)c8 * 2u;
            uint32_t sw  = off ^ ((off >> 3) & 0x70);
            *(uint4*)(smem + AH_OFF + sw) = pack8h(f0, f1);
        }
        __syncthreads();

        // ---- MMA: 8 m-chunks of 16 tokens; single fp16 product ----
        #pragma unroll 2
        for (int m = 0; m < 8; m++) {
            float acc[16];
            #pragma unroll
            for (int i = 0; i < 16; i++) acc[i] = 0.f;

            #pragma unroll
            for (int ks = 0; ks < 4; ks++) {
                int row = m * 16 + (mat & 1) * 8 + r8;
                int bc  = ks * 32 + (mat >> 1) * 16;
                uint32_t ah[4];
                ldsm4(swaddr(sbase + AH_OFF, row, bc), ah);
                #pragma unroll
                for (int nf = 0; nf < 4; nf++) mma16816(&acc[nf*4], ah, &bh[ks][nf*2]);
            }

            // per-token top-2 over 32 codes: pair-propagating IMNMX
            #pragma unroll
            for (int half = 0; half < 2; half++) {
                uint32_t p1[4], p2[4];
                #pragma unroll
                for (int nf = 0; nf < 4; nf++) {
                    float s0 = __fmaf_rn(-2.f, acc[nf*4 + half*2 + 0], bnr[nf*2 + 0]);
                    float s1 = __fmaf_rn(-2.f, acc[nf*4 + half*2 + 1], bnr[nf*2 + 1]);
                    uint32_t k0 = (__float_as_uint(__fadd_rn(s0, 8.5f)) << 9)
                                | (uint32_t)(wbase + nf*8 + c2);
                    uint32_t k1 = (__float_as_uint(__fadd_rn(s1, 8.5f)) << 9)
                                | (uint32_t)(wbase + nf*8 + c2 + 1);
                    p1[nf] = min(k0, k1); p2[nf] = max(k0, k1);
                }
                uint32_t m1a = min(p1[0], p1[1]);
                uint32_t m2a = min(max(p1[0], p1[1]), min(p2[0], p2[1]));
                uint32_t m1b = min(p1[2], p1[3]);
                uint32_t m2b = min(max(p1[2], p1[3]), min(p2[2], p2[3]));
                uint32_t m1 = min(m1a, m1b);
                uint32_t m2 = min(max(m1a, m1b), min(m2a, m2b));
                #pragma unroll
                for (int off = 1; off <= 2; off <<= 1) {
                    uint32_t o1 = __shfl_xor_sync(0xffffffffu, m1, off);
                    uint32_t o2 = __shfl_xor_sync(0xffffffffu, m2, off);
                    uint32_t nm1 = min(m1, o1);
                    m2 = min(max(m1, o1), min(m2, o2));
                    m1 = nm1;
                }
                if ((lane & 3) == 0) {
                    int tok = m * 16 + half * 8 + (lane >> 2);
                    cand[wid * 128 + tok] = make_uint2(m1, m2);
                }
            }
        }
        __syncthreads();

        // ---- merge top-4 of 32 packed keys (token = tid < 128) ----
        if (tid < TM) {
            uint32_t key[32];
            #pragma unroll
            for (int w = 0; w < 16; w++) {
                uint2 c = cand[w * 128 + tid];
                key[w * 2] = c.x; key[w * 2 + 1] = c.y;
            }
            #pragma unroll
            for (int p = 0; p < 4; p++) {
                uint32_t t16[16];
                #pragma unroll
                for (int i = 0; i < 16; i++) t16[i] = min(key[i], key[i + 16]);
                #pragma unroll
                for (int i = 0; i < 8; i++) t16[i] = min(t16[i], t16[i + 8]);
                #pragma unroll
                for (int i = 0; i < 4; i++) t16[i] = min(t16[i], t16[i + 4]);
                uint32_t mn = min(min(t16[0], t16[1]), min(t16[2], t16[3]));
                kcs[tid * 4 + p] = (int)(mn & 511u);
                #pragma unroll
                for (int i = 0; i < 32; i++)
                    if (key[i] == mn) key[i] = 0xFFFFFFFFu;
            }
        }
        __syncthreads();

        // ---- exact rescoring: 4 threads per token, one candidate each ----
        {
            const int tok = tid >> 2;
            const int ci  = tid & 3;
            const int kc  = kcs[tok * 4 + ci];
            const float* xp = xs + tok * XSTRIDE;
            float A = 0.f;   // exact reference-order ||x||^2
            #pragma unroll
            for (int i = 0; i < DN; i++) A = __fadd_rn(A, __fmul_rn(xp[i], xp[i]));
            float bd = exact_d(xp, emb, A, bn[kc], kc);
            int   bk = kc;
            #pragma unroll
            for (int off = 1; off <= 2; off <<= 1) {
                float od = __shfl_xor_sync(0xffffffffu, bd, off);
                int   ok = __shfl_xor_sync(0xffffffffu, bk, off);
                if (od < bd || (od == bd && ok < bk)) { bd = od; bk = ok; }
            }
            if (ci == 0) {
                ka[tok] = bk;
                out_idx[tok0 + tok] = (float)bk;
                atomicAdd(&hist[bk], 1u);
            }
        }
        __syncthreads();

        // ---- gather + straight-through write + err sum (16 warps x 8 tokens) ----
        float err = 0.f;
        #pragma unroll 2
        for (int t = wid * 8; t < wid * 8 + 8; t++) {
            int k = ka[t];
            const float* er = emb + (size_t)k * DN;
            const float* xr = xs + t * XSTRIDE;
            float x0 = xr[lane], x1 = xr[32 + lane];
            float q0 = __ldg(er + lane), q1 = __ldg(er + 32 + lane);
            float d0 = __fsub_rn(q0, x0);
            float d1 = __fsub_rn(q1, x1);
            out_q[(size_t)(tok0 + t) * DN + lane]      = __fadd_rn(x0, d0);
            out_q[(size_t)(tok0 + t) * DN + 32 + lane] = __fadd_rn(x1, d1);
            err = __fmaf_rn(d0, d0, __fmaf_rn(d1, d1, err));
        }
        #pragma unroll
        for (int off = 16; off > 0; off >>= 1)
            err += __shfl_xor_sync(0xffffffffu, err, off);
        errd += (double)err;
        __syncthreads();
    }

    // ---- flush per-CTA accumulators ----
    if (lane == 0) atomicAdd(&g_err_sum, errd);
    for (int t = tid; t < KN; t += NTHREADS) {
        unsigned int c = hist[t];
        if (c) atomicAdd(&g_counts[t], c);
    }
    __threadfence();
    __syncthreads();

    // ---- last CTA: loss + perplexity, then reset for next graph replay ----
    __shared__ unsigned int s_last;
    __shared__ float s_red[NTHREADS / 32];
    if (tid == 0)
        s_last = (atomicAdd(&g_done, 1u) == (unsigned)(gridDim.x - 1)) ? 1u : 0u;
    __syncthreads();
    if (s_last) {
        float part = 0.f;
        const float invN = 1.0f / (float)ntok;
        for (int k = tid; k < KN; k += NTHREADS) {
            unsigned int c = atomicAdd(&g_counts[k], 0u);
            g_counts[k] = 0u;
            float p = __fmul_rn((float)c, invN);
            part = __fmaf_rn(p, logf(__fadd_rn(p, 1e-10f)), part);
        }
        #pragma unroll
        for (int off = 16; off > 0; off >>= 1)
            part += __shfl_xor_sync(0xffffffffu, part, off);
        if (lane == 0) s_red[wid] = part;
        __syncthreads();
        if (tid == 0) {
            float sum = 0.f;
            #pragma unroll
            for (int w = 0; w < NTHREADS / 32; w++) sum += s_red[w];
            double esum = atomicAdd(&g_err_sum, 0.0);
            float m = (float)(esum / ((double)ntok * (double)DN));
            out[0]      = __fadd_rn(m, __fmul_rn(0.25f, m));
            out_perp[0] = expf(-sum);
            g_err_sum = 0.0;
            g_done = 0u;
        }
    }
}

extern "C" void kernel_launch(void* const* d_in, const int* in_sizes, int n_in,
                              void* d_out, int out_size)
{
    const float* x   = (const float*)d_in[0];
    const float* emb = (const float*)d_in[1];
    const int ntok = in_sizes[0] / DN;   // 65536

    cudaFuncSetAttribute(vq_all, cudaFuncAttributeMaxDynamicSharedMemorySize, SMEM_TOTAL);
    vq_all<<<NBLK, NTHREADS, SMEM_TOTAL>>>(x, emb, (float*)d_out, ntok);
}

// round 9
// speedup vs baseline: 5.4709x; 1.2010x over previous
#include <cuda_runtime.h>
#include <cuda_fp16.h>
#include <cstdint>

// Fused VQ forward: fp16 HMMA GEMM + margin-gated exact fp32 rescoring.
// Gap bound: |approx-ref| score error <= ~3.9e-4 (hard C-S bound) => if the
// packed-key top-2 gap > MARGIN, approx argmin == reference argmin (proof in
// analysis); else run the validated exact top-4 rescore.
//   inputs [64,1024,64] f32, embedding [512,64] f32
//   out = [loss(1) | quantized_st(65536*64) | perplexity(1) | indices(65536)] f32

#define KN 512
#define DN 64
#define TM 128
#define XSTRIDE 68
#define NTHREADS 512
#define NBLK 148
#define MARGIN_KEYS 900   // ~8.6e-4 in score units (key ulp = 9.537e-7)

// ---- smem layout (bytes) ----
#define AH_OFF    0            // [128 x 128B] X fp16 (SW128)
#define BH_OFF    16384        // [512 x 128B] E fp16 (SW128)
#define XS_OFF    81920        // [128 x 68] f32 staged X
#define BN_OFF    116736       // [512] f32 ||e||^2
#define KA_OFF    118784       // [128] int chosen code
#define HIST_OFF  119296       // [512] u32
#define CAND_OFF  121344       // [16][129] uint2 (padded stride: conflict-free)
#define SMEM_TOTAL 137984

__device__ double       g_err_sum;
__device__ unsigned int g_counts[KN];
__device__ unsigned int g_done;

__device__ __forceinline__ uint32_t smem_u32(const void* p) {
    uint32_t a;
    asm("{ .reg .u64 t; cvta.to.shared.u64 t, %1; cvt.u32.u64 %0, t; }" : "=r"(a) : "l"(p));
    return a;
}
__device__ __forceinline__ void ldsm4(uint32_t addr, uint32_t* r) {
    asm volatile("ldmatrix.sync.aligned.m8n8.x4.shared.b16 {%0,%1,%2,%3}, [%4];"
                 : "=r"(r[0]), "=r"(r[1]), "=r"(r[2]), "=r"(r[3]) : "r"(addr));
}
__device__ __forceinline__ void mma16816(float* d, const uint32_t* a, const uint32_t* b) {
    asm volatile("mma.sync.aligned.m16n8k16.row.col.f32.f16.f16.f32 "
                 "{%0,%1,%2,%3}, {%4,%5,%6,%7}, {%8,%9}, {%0,%1,%2,%3};"
                 : "+f"(d[0]), "+f"(d[1]), "+f"(d[2]), "+f"(d[3])
                 : "r"(a[0]), "r"(a[1]), "r"(a[2]), "r"(a[3]), "r"(b[0]), "r"(b[1]));
}
__device__ __forceinline__ uint32_t swaddr(uint32_t base, int row, int bc) {
    return base + row * 128 + (bc ^ ((row & 7) << 4));
}

__device__ __forceinline__ uint4 pack8h(const float4 a, const float4 b) {
    __half2 h0 = __floats2half2_rn(a.x, a.y);
    __half2 h1 = __floats2half2_rn(a.z, a.w);
    __half2 h2 = __floats2half2_rn(b.x, b.y);
    __half2 h3 = __floats2half2_rn(b.z, b.w);
    uint4 r;
    r.x = *reinterpret_cast<uint32_t*>(&h0);
    r.y = *reinterpret_cast<uint32_t*>(&h1);
    r.z = *reinterpret_cast<uint32_t*>(&h2);
    r.w = *reinterpret_cast<uint32_t*>(&h3);
    return r;
}

// exact reference-order distance (validated flip-free vs reference)
__device__ __forceinline__ float exact_d(const float* __restrict__ xp,
                                         const float* __restrict__ emb,
                                         float A, float bnk, int k) {
    const float4* ep = (const float4*)(emb + (size_t)k * DN);
    float dot = 0.f;
    #pragma unroll
    for (int i = 0; i < 16; i++) {
        float4 e4 = __ldg(ep + i);
        const float4 x4 = *(const float4*)(xp + 4 * i);
        dot = __fmaf_rn(x4.x, e4.x, dot);
        dot = __fmaf_rn(x4.y, e4.y, dot);
        dot = __fmaf_rn(x4.z, e4.z, dot);
        dot = __fmaf_rn(x4.w, e4.w, dot);
    }
    return __fsub_rn(__fadd_rn(A, bnk), __fmul_rn(2.0f, dot));
}

__global__ void __launch_bounds__(NTHREADS, 1)
vq_all(const float* __restrict__ x, const float* __restrict__ emb,
       float* __restrict__ out, int ntok)
{
    extern __shared__ __align__(1024) char smem[];
    const uint32_t sbase = smem_u32(smem);
    const int tid  = threadIdx.x;
    const int lane = tid & 31;
    const int wid  = tid >> 5;

    float* out_q    = out + 1;
    float* out_perp = out + 1 + (size_t)ntok * DN;
    float* out_idx  = out + 2 + (size_t)ntok * DN;

    float* xs = (float*)(smem + XS_OFF);
    float* bn = (float*)(smem + BN_OFF);
    int*   ka = (int*)(smem + KA_OFF);
    unsigned int* hist = (unsigned int*)(smem + HIST_OFF);
    uint2* cand = (uint2*)(smem + CAND_OFF);   // [16][129] padded

    // ---- once per CTA: convert E to fp16 SW128 + exact norms + zero hist ----
    for (int idx = tid; idx < KN * DN / 8; idx += NTHREADS) {
        int row = idx >> 3;
        int c8  = (idx & 7) * 8;
        const float* gp = emb + (size_t)row * DN + c8;
        float4 f0 = __ldg((const float4*)gp);
        float4 f1 = __ldg((const float4*)gp + 1);
        uint32_t off = (uint32_t)row * 128u + (uint32_t)c8 * 2u;
        uint32_t sw  = off ^ ((off >> 3) & 0x70);
        *(uint4*)(smem + BH_OFF + sw) = pack8h(f0, f1);
    }
    for (int k = tid; k < KN; k += NTHREADS) {
        const float* ep = emb + (size_t)k * DN;
        float s = 0.f;
        #pragma unroll
        for (int i = 0; i < DN; i++) s = __fadd_rn(s, __fmul_rn(ep[i], ep[i]));
        bn[k] = s;
    }
    for (int t = tid; t < KN; t += NTHREADS) hist[t] = 0u;
    __syncthreads();

    const int wbase = wid * 32;
    const int r8  = lane & 7;
    const int mat = lane >> 3;
    const int c2  = (lane & 3) * 2;

    float bnr[8];
    #pragma unroll
    for (int nf = 0; nf < 4; nf++) {
        bnr[nf * 2]     = bn[wbase + nf * 8 + c2];
        bnr[nf * 2 + 1] = bn[wbase + nf * 8 + c2 + 1];
    }

    // ---- register-cache B fragments (fp16) for this warp's 32 codes ----
    uint32_t bh[4][8];
    #pragma unroll
    for (int ks = 0; ks < 4; ks++) {
        #pragma unroll
        for (int q = 0; q < 2; q++) {
            int row = wbase + q * 16 + (mat >> 1) * 8 + r8;
            int bc  = ks * 32 + (mat & 1) * 16;
            uint32_t t4[4];
            ldsm4(swaddr(sbase + BH_OFF, row, bc), t4);
            bh[ks][q*4+0] = t4[0]; bh[ks][q*4+1] = t4[1];
            bh[ks][q*4+2] = t4[2]; bh[ks][q*4+3] = t4[3];
        }
    }

    double errd = 0.0;
    const int ntile = ntok / TM;

    for (int tile = blockIdx.x; tile < ntile; tile += gridDim.x) {
        const int tok0 = tile * TM;

        // ---- convert X tile to fp16 + stage f32 ----
        for (int idx = tid; idx < TM * DN / 8; idx += NTHREADS) {
            int row = idx >> 3;
            int c8  = (idx & 7) * 8;
            const float* gp = x + (size_t)(tok0 + row) * DN + c8;
            float4 f0 = __ldg((const float4*)gp);
            float4 f1 = __ldg((const float4*)gp + 1);
            float* xr = xs + row * XSTRIDE + c8;
            *(float4*)xr = f0; *(float4*)(xr + 4) = f1;
            uint32_t off = (uint32_t)row * 128u + (uint32_t)c8 * 2u;
            uint32_t sw  = off ^ ((off >> 3) & 0x70);
            *(uint4*)(smem + AH_OFF + sw) = pack8h(f0, f1);
        }
        __syncthreads();

        // ---- MMA: 8 m-chunks of 16 tokens; single fp16 product ----
        #pragma unroll 2
        for (int m = 0; m < 8; m++) {
            float acc[16];
            #pragma unroll
            for (int i = 0; i < 16; i++) acc[i] = 0.f;

            #pragma unroll
            for (int ks = 0; ks < 4; ks++) {
                int row = m * 16 + (mat & 1) * 8 + r8;
                int bc  = ks * 32 + (mat >> 1) * 16;
                uint32_t ah[4];
                ldsm4(swaddr(sbase + AH_OFF, row, bc), ah);
                #pragma unroll
                for (int nf = 0; nf < 4; nf++) mma16816(&acc[nf*4], ah, &bh[ks][nf*2]);
            }

            // per-token top-2 over 32 codes: pair-propagating IMNMX
            #pragma unroll
            for (int half = 0; half < 2; half++) {
                uint32_t p1[4], p2[4];
                #pragma unroll
                for (int nf = 0; nf < 4; nf++) {
                    float s0 = __fmaf_rn(-2.f, acc[nf*4 + half*2 + 0], bnr[nf*2 + 0]);
                    float s1 = __fmaf_rn(-2.f, acc[nf*4 + half*2 + 1], bnr[nf*2 + 1]);
                    uint32_t k0 = (__float_as_uint(__fadd_rn(s0, 8.5f)) << 9)
                                | (uint32_t)(wbase + nf*8 + c2);
                    uint32_t k1 = (__float_as_uint(__fadd_rn(s1, 8.5f)) << 9)
                                | (uint32_t)(wbase + nf*8 + c2 + 1);
                    p1[nf] = min(k0, k1); p2[nf] = max(k0, k1);
                }
                uint32_t m1a = min(p1[0], p1[1]);
                uint32_t m2a = min(max(p1[0], p1[1]), min(p2[0], p2[1]));
                uint32_t m1b = min(p1[2], p1[3]);
                uint32_t m2b = min(max(p1[2], p1[3]), min(p2[2], p2[3]));
                uint32_t m1 = min(m1a, m1b);
                uint32_t m2 = min(max(m1a, m1b), min(m2a, m2b));
                #pragma unroll
                for (int off = 1; off <= 2; off <<= 1) {
                    uint32_t o1 = __shfl_xor_sync(0xffffffffu, m1, off);
                    uint32_t o2 = __shfl_xor_sync(0xffffffffu, m2, off);
                    uint32_t nm1 = min(m1, o1);
                    m2 = min(max(m1, o1), min(m2, o2));
                    m1 = nm1;
                }
                if ((lane & 3) == 0) {
                    int tok = m * 16 + half * 8 + (lane >> 2);
                    cand[wid * 129 + tok] = make_uint2(m1, m2);
                }
            }
        }
        __syncthreads();

        // ---- merge: global top-2 + margin gate; rare exact top-4 rescore ----
        {
            const int tok = tid >> 2;
            const int ci  = tid & 3;
            const uint32_t qmask = 0xFu << (lane & 28);

            uint32_t p1[4], p2[4];
            #pragma unroll
            for (int w = 0; w < 4; w++) {
                uint2 c = cand[(ci * 4 + w) * 129 + tok];
                p1[w] = c.x; p2[w] = c.y;      // already ordered per warp
            }
            uint32_t a1 = min(p1[0], p1[1]);
            uint32_t a2 = min(max(p1[0], p1[1]), min(p2[0], p2[1]));
            uint32_t b1 = min(p1[2], p1[3]);
            uint32_t b2 = min(max(p1[2], p1[3]), min(p2[2], p2[3]));
            uint32_t m1 = min(a1, b1);
            uint32_t m2 = min(max(a1, b1), min(a2, b2));
            #pragma unroll
            for (int off = 1; off <= 2; off <<= 1) {
                uint32_t o1 = __shfl_xor_sync(0xffffffffu, m1, off);
                uint32_t o2 = __shfl_xor_sync(0xffffffffu, m2, off);
                uint32_t n1 = min(m1, o1);
                m2 = min(max(m1, o1), min(m2, o2));
                m1 = n1;
            }

            int gap = (int)(m2 >> 9) - (int)(m1 >> 9);
            int bk;
            if (gap > MARGIN_KEYS) {
                bk = (int)(m1 & 511u);          // provably the reference argmin
            } else {
                // rare path: top-4 of all 32 keys, exact rescoring (quad-split)
                uint32_t key[32];
                #pragma unroll
                for (int w = 0; w < 16; w++) {
                    uint2 c = cand[w * 129 + tok];
                    key[2*w] = c.x; key[2*w+1] = c.y;
                }
                int kc = 0;
                #pragma unroll
                for (int p = 0; p < 4; p++) {
                    uint32_t t16[16];
                    #pragma unroll
                    for (int i = 0; i < 16; i++) t16[i] = min(key[i], key[i + 16]);
                    #pragma unroll
                    for (int i = 0; i < 8; i++) t16[i] = min(t16[i], t16[i + 8]);
                    #pragma unroll
                    for (int i = 0; i < 4; i++) t16[i] = min(t16[i], t16[i + 4]);
                    uint32_t mn = min(min(t16[0], t16[1]), min(t16[2], t16[3]));
                    if (p == ci) kc = (int)(mn & 511u);
                    #pragma unroll
                    for (int i = 0; i < 32; i++)
                        if (key[i] == mn) key[i] = 0xFFFFFFFFu;
                }
                const float* xp = xs + tok * XSTRIDE;
                float A = 0.f;    // exact reference-order ||x||^2
                #pragma unroll
                for (int i = 0; i < DN; i++) A = __fadd_rn(A, __fmul_rn(xp[i], xp[i]));
                float bd = exact_d(xp, emb, A, bn[kc], kc);
                bk = kc;
                #pragma unroll
                for (int off = 1; off <= 2; off <<= 1) {
                    float od = __shfl_xor_sync(qmask, bd, off);
                    int   ok = __shfl_xor_sync(qmask, bk, off);
                    if (od < bd || (od == bd && ok < bk)) { bd = od; bk = ok; }
                }
            }
            if (ci == 0) {
                ka[tok] = bk;
                out_idx[tok0 + tok] = (float)bk;
                atomicAdd(&hist[bk], 1u);
            }
        }
        __syncthreads();

        // ---- gather + straight-through write + err sum (16 warps x 8 tokens) ----
        float err = 0.f;
        #pragma unroll 2
        for (int t = wid * 8; t < wid * 8 + 8; t++) {
            int k = ka[t];
            const float* er = emb + (size_t)k * DN;
            const float* xr = xs + t * XSTRIDE;
            float x0 = xr[lane], x1 = xr[32 + lane];
            float q0 = __ldg(er + lane), q1 = __ldg(er + 32 + lane);
            float d0 = __fsub_rn(q0, x0);
            float d1 = __fsub_rn(q1, x1);
            out_q[(size_t)(tok0 + t) * DN + lane]      = __fadd_rn(x0, d0);
            out_q[(size_t)(tok0 + t) * DN + 32 + lane] = __fadd_rn(x1, d1);
            err = __fmaf_rn(d0, d0, __fmaf_rn(d1, d1, err));
        }
        #pragma unroll
        for (int off = 16; off > 0; off >>= 1)
            err += __shfl_xor_sync(0xffffffffu, err, off);
        errd += (double)err;
        __syncthreads();
    }

    // ---- flush per-CTA accumulators ----
    if (lane == 0) atomicAdd(&g_err_sum, errd);
    for (int t = tid; t < KN; t += NTHREADS) {
        unsigned int c = hist[t];
        if (c) atomicAdd(&g_counts[t], c);
    }
    __threadfence();
    __syncthreads();

    // ---- last CTA: loss + perplexity, then reset for next graph replay ----
    __shared__ unsigned int s_last;
    __shared__ float s_red[NTHREADS / 32];
    if (tid == 0)
        s_last = (atomicAdd(&g_done, 1u) == (unsigned)(gridDim.x - 1)) ? 1u : 0u;
    __syncthreads();
    if (s_last) {
        float part = 0.f;
        const float invN = 1.0f / (float)ntok;
        for (int k = tid; k < KN; k += NTHREADS) {
            unsigned int c = atomicAdd(&g_counts[k], 0u);
            g_counts[k] = 0u;
            float p = __fmul_rn((float)c, invN);
            part = __fmaf_rn(p, logf(__fadd_rn(p, 1e-10f)), part);
        }
        #pragma unroll
        for (int off = 16; off > 0; off >>= 1)
            part += __shfl_xor_sync(0xffffffffu, part, off);
        if (lane == 0) s_red[wid] = part;
        __syncthreads();
        if (tid == 0) {
            float sum = 0.f;
            #pragma unroll
            for (int w = 0; w < NTHREADS / 32; w++) sum += s_red[w];
            double esum = atomicAdd(&g_err_sum, 0.0);
            float m = (float)(esum / ((double)ntok * (double)DN));
            out[0]      = __fadd_rn(m, __fmul_rn(0.25f, m));
            out_perp[0] = expf(-sum);
            g_err_sum = 0.0;
            g_done = 0u;
        }
    }
}

extern "C" void kernel_launch(void* const* d_in, const int* in_sizes, int n_in,
                              void* d_out, int out_size)
{
    const float* x   = (const float*)d_in[0];
    const float* emb = (const float*)d_in[1];
    const int ntok = in_sizes[0] / DN;   // 65536

    cudaFuncSetAttribute(vq_all, cudaFuncAttributeMaxDynamicSharedMemorySize, SMEM_TOTAL);
    vq_all<<<NBLK, NTHREADS, SMEM_TOTAL>>>(x, emb, (float*)d_out, ntok);
}